// round 9
// baseline (speedup 1.0000x reference)
#include <cuda_runtime.h>
#include <cstdint>

#define IC_   128
#define OC_   128
#define ZDIM_ 256
#define B_    16
#define WSIZE_ (OC_ * IC_ * 9)   // 147456

// Per-sample weights in m16n8k8 A-fragment order (paired-k mapping):
// [b][chunk j=icc*9+tap (36)][m16-tile (8)][ks (4)][lane (32)][reg (4)]
// k-slot (tg,h) <-> ic_local = ks*8 + 2*tg + h   (h: 0 -> k=tg, 1 -> k=tg+4)
__device__ float g_w[(size_t)B_ * WSIZE_];

__device__ __forceinline__ float to_tf32(float v) {
    float o;
    asm("cvt.rna.tf32.f32 %0, %1;" : "=f"(o) : "f"(v));
    return o;
}

__device__ __forceinline__ uint32_t smem_u32(const void* p) {
    uint32_t a;
    asm("{ .reg .u64 t; cvta.to.shared.u64 t, %1; cvt.u32.u64 %0, t; }" : "=r"(a) : "l"(p));
    return a;
}

__device__ __forceinline__ void cp_async16(uint32_t dst, const void* src) {
    asm volatile("cp.async.cg.shared.global [%0], [%1], 16;" :: "r"(dst), "l"(src));
}

// ---------------------------------------------------------------------------
// Kernel 1: per-sample weight generation (R6 version: coalesced reads,
// vectorized SMEM, scattered fragment-order writes). ~38us measured.
// ---------------------------------------------------------------------------
__global__ __launch_bounds__(256) void weight_kernel(
    const float* __restrict__ z, const float* __restrict__ base_w,
    const float* __restrict__ head_w, const float* __restrict__ head_b)
{
    __shared__ float zt[ZDIM_ * B_];        // z transposed: [d][b]
    __shared__ float hw_s[2][256 * 20];     // double-buffered, pitch 20

    const int tid = threadIdx.x;
    const int m0  = blockIdx.x * 256;

    for (int i = tid; i < B_ * ZDIM_; i += 256) {
        int b = i >> 8;
        int d = i & 255;
        zt[d * B_ + b] = z[i];
    }

    const int mg = tid & 63;
    const int bg = tid >> 6;

    float acc[4][4];
#pragma unroll
    for (int i = 0; i < 4; i++)
#pragma unroll
        for (int j = 0; j < 4; j++) acc[i][j] = 0.f;

    float4 ar[4];
    auto ldg_tile = [&](int dc) {
#pragma unroll
        for (int k = 0; k < 4; k++) {
            int t4 = tid + k * 256;
            int m  = t4 >> 2;
            int d4 = t4 & 3;
            ar[k] = *reinterpret_cast<const float4*>(
                &head_w[(size_t)(m0 + m) * ZDIM_ + dc * 16 + d4 * 4]);
        }
    };
    auto sts_tile = [&](int buf) {
#pragma unroll
        for (int k = 0; k < 4; k++) {
            int t4 = tid + k * 256;
            int m  = t4 >> 2;
            int d4 = t4 & 3;
            *reinterpret_cast<float4*>(&hw_s[buf][m * 20 + d4 * 4]) = ar[k];
        }
    };

    ldg_tile(0);
    sts_tile(0);
    ldg_tile(1);
    __syncthreads();

    for (int dc = 0; dc < 16; dc++) {
        const float* hb = hw_s[dc & 1];
#pragma unroll
        for (int d4 = 0; d4 < 4; d4++) {
            float hq[4][4];
#pragma unroll
            for (int i = 0; i < 4; i++)
                *reinterpret_cast<float4*>(hq[i]) =
                    *reinterpret_cast<const float4*>(&hb[(mg + 64 * i) * 20 + d4 * 4]);
            float zq[4][4];
#pragma unroll
            for (int e = 0; e < 4; e++)
                *reinterpret_cast<float4*>(zq[e]) =
                    *reinterpret_cast<const float4*>(&zt[(dc * 16 + d4 * 4 + e) * B_ + bg * 4]);
#pragma unroll
            for (int e = 0; e < 4; e++)
#pragma unroll
                for (int i = 0; i < 4; i++)
#pragma unroll
                    for (int j = 0; j < 4; j++)
                        acc[i][j] += hq[i][e] * zq[e][j];
        }
        if (dc < 15) {
            sts_tile((dc + 1) & 1);
            if (dc + 2 < 16) ldg_tile(dc + 2);
            __syncthreads();
        }
    }

    // scatter to fragment-order layout (paired-k mapping)
#pragma unroll
    for (int i = 0; i < 4; i++) {
        int m   = m0 + mg + 64 * i;
        int oc  = m / 1152;
        int rem = m - oc * 1152;
        int ic  = rem / 9;
        int tap = rem - ic * 9;
        float bb = base_w[m] + head_b[m];

        int jc   = (ic >> 5) * 9 + tap;
        int k    = ic & 31;
        int ks   = k >> 3;
        int k8   = k & 7;
        int tile = oc >> 4;
        int m16  = oc & 15;
        int lane = (m16 & 7) * 4 + (k8 >> 1);
        int reg  = (m16 >> 3) + 2 * (k8 & 1);
        size_t off = (size_t)jc * 4096 + tile * 512 + ks * 128 + lane * 4 + reg;
#pragma unroll
        for (int j = 0; j < 4; j++) {
            int b = bg * 4 + j;
            g_w[((size_t)b * 36) * 4096 + off] = to_tf32(bb + acc[i][j]);
        }
    }
}

// ---------------------------------------------------------------------------
// Kernel 2: implicit-GEMM conv on mma.sync tf32 (HMMA).
// CTA tile: M=128 oc x N=128 px (2 rows x 64 cols) x K=1152 (36 chunks of 32).
// 8 warps 4x2: each 32 oc x 64 px.
// A: per-warp PRIVATE 2-stage cp.async buffer, wait_group-paced, no barriers.
// B: xs in [rowl 4][c0 10][G 8][ic 32 + 8pad] layout (floats); one LDS.64
//    yields (b0,b1) for a lane (paired-k). Conflict-free by construction.
// SMEM floats: A 16384, xs at 16384 (10560 fl). 105.25 KB dynamic.
// ---------------------------------------------------------------------------
#define XS_OFF    16384
#define SM_FLOATS (16384 + 10560)

__device__ __forceinline__ void mma_tf32(float* d, const uint32_t* a,
                                         uint32_t b0, uint32_t b1) {
    asm volatile(
        "mma.sync.aligned.m16n8k8.row.col.f32.tf32.tf32.f32 "
        "{%0,%1,%2,%3}, {%4,%5,%6,%7}, {%8,%9}, {%0,%1,%2,%3};"
        : "+f"(d[0]), "+f"(d[1]), "+f"(d[2]), "+f"(d[3])
        : "r"(a[0]), "r"(a[1]), "r"(a[2]), "r"(a[3]), "r"(b0), "r"(b1));
}

__global__ __launch_bounds__(256, 2) void conv_kernel(
    const float* __restrict__ x, float* __restrict__ out)
{
    extern __shared__ float sm[];
    float* xs = sm + XS_OFF;
    const uint32_t smb = smem_u32(sm);

    const int tid  = threadIdx.x;
    const int wid  = tid >> 5;
    const int lid  = tid & 31;
    const int g    = lid >> 2;        // 0..7
    const int tg   = lid & 3;         // 0..3
    const int wm   = wid & 3;         // oc quarter (32 oc)
    const int wn   = wid >> 2;        // output row within pair
    const int pair = blockIdx.x;      // 0..31
    const int b    = blockIdx.y;      // 0..15
    const int r0   = pair * 2;

    const float* xb    = x + (size_t)b * IC_ * 4096;
    const float* wbase = g_w + ((size_t)b * 36) * 4096;

    float acc[2][8][4];
#pragma unroll
    for (int mt = 0; mt < 2; mt++)
#pragma unroll
        for (int nt = 0; nt < 8; nt++)
#pragma unroll
            for (int r = 0; r < 4; r++) acc[mt][nt][r] = 0.f;

    // xs[rowl][c0][G][ic]: slot holds x[ic][r0-1+rowl][8G + c0 - 1] (tf32)
    // strides: ic 1, G 32, c0 264, rowl 2640
    auto build_xs = [&](int icc) {
        for (int idx = tid; idx < 4 * 32 * 66; idx += 256) {
            int rowl = idx / 2112;            // 32*66
            int rem  = idx - rowl * 2112;
            int ic   = rem / 66;
            int p    = rem - ic * 66;         // p = pixel + 1, 0..65
            int gr   = r0 - 1 + rowl;
            int px   = p - 1;
            float v = 0.f;
            if ((unsigned)gr < 64u && (unsigned)px < 64u)
                v = xb[(size_t)(icc * 32 + ic) * 4096 + gr * 64 + px];
            v = to_tf32(v);
            int G  = p >> 3;
            int c0 = p & 7;
            float* base = xs + rowl * 2640 + ic;
            if (p < 64)             base[c0 * 264 + G * 32]             = v;
            if (c0 < 2 && p >= 8)   base[(c0 + 8) * 264 + (G - 1) * 32] = v;
        }
    };

    // per-warp private A copy: this warp's 1024 fragment floats of chunk j
    const uint32_t aw_dst0 = smb + (wid * 2048 + lid * 4) * 4;
    auto cpA = [&](int j) {
        const float* src = wbase + (size_t)j * 4096 + wm * 1024 + lid * 4;
        uint32_t dst = aw_dst0 + (j & 1) * 4096;
#pragma unroll
        for (int i = 0; i < 8; i++)
            cp_async16(dst + i * 512, src + i * 128);
        asm volatile("cp.async.commit_group;" ::: "memory");
    };

    auto mma_chunk = [&](int stage, int kh, int kw) {
        const float* As = sm + wid * 2048 + stage * 1024 + lid * 4;
        const float* xw = xs + (wn + kh) * 2640 + (g + kw) * 264 + 2 * tg;
#pragma unroll
        for (int ks = 0; ks < 4; ks++) {
            float4 fa0 = *reinterpret_cast<const float4*>(As + ks * 128);
            float4 fa1 = *reinterpret_cast<const float4*>(As + 512 + ks * 128);
            uint32_t a0[4], a1[4];
            a0[0] = __float_as_uint(fa0.x); a0[1] = __float_as_uint(fa0.y);
            a0[2] = __float_as_uint(fa0.z); a0[3] = __float_as_uint(fa0.w);
            a1[0] = __float_as_uint(fa1.x); a1[1] = __float_as_uint(fa1.y);
            a1[2] = __float_as_uint(fa1.z); a1[3] = __float_as_uint(fa1.w);
            const float* xk = xw + ks * 8;
#pragma unroll
            for (int nt = 0; nt < 8; nt++) {
                float2 bv = *reinterpret_cast<const float2*>(xk + nt * 32);
                uint32_t b0 = __float_as_uint(bv.x);
                uint32_t b1 = __float_as_uint(bv.y);
                mma_tf32(acc[0][nt], a0, b0, b1);
                mma_tf32(acc[1][nt], a1, b0, b1);
            }
        }
    };

    // ---- prologue ----
    cpA(0);
    cpA(1);
    build_xs(0);
    __syncthreads();

    // ---- main loop: NO CTA barriers inside icc groups ----
    for (int icc = 0; icc < 4; icc++) {
#pragma unroll
        for (int tap = 0; tap < 9; tap++) {
            const int j  = icc * 9 + tap;
            const int kh = tap / 3;
            const int kw = tap - kh * 3;

            if (j < 34)
                asm volatile("cp.async.wait_group 1;" ::: "memory");
            else
                asm volatile("cp.async.wait_group 0;" ::: "memory");

            mma_chunk(j & 1, kh, kw);

            if (j + 2 < 36) cpA(j + 2);
        }
        if (icc < 3) {
            __syncthreads();          // all warps done reading xs
            build_xs(icc + 1);
            __syncthreads();
        }
    }

    // ---- epilogue: acc -> out[b][oc][px] ----
#pragma unroll
    for (int mt = 0; mt < 2; mt++) {
        int oc = wm * 32 + mt * 16 + g;
#pragma unroll
        for (int nt = 0; nt < 8; nt++) {
            int n  = wn * 64 + nt * 8 + 2 * tg;
            size_t base = ((size_t)b * OC_ + oc) * 4096 + pair * 128 + n;
            float2 v0 = make_float2(acc[mt][nt][0], acc[mt][nt][1]);
            float2 v1 = make_float2(acc[mt][nt][2], acc[mt][nt][3]);
            *reinterpret_cast<float2*>(out + base)            = v0;
            *reinterpret_cast<float2*>(out + base + 8 * 4096) = v1;
        }
    }
}

// ---------------------------------------------------------------------------
extern "C" void kernel_launch(void* const* d_in, const int* in_sizes, int n_in,
                              void* d_out, int out_size) {
    const float* x      = (const float*)d_in[0];
    const float* z      = (const float*)d_in[1];
    const float* base_w = (const float*)d_in[2];
    const float* head_w = (const float*)d_in[3];
    const float* head_b = (const float*)d_in[4];
    float* out = (float*)d_out;

    static bool attr_set = false;
    if (!attr_set) {
        cudaFuncSetAttribute(conv_kernel,
                             cudaFuncAttributeMaxDynamicSharedMemorySize,
                             SM_FLOATS * 4);
        attr_set = true;
    }

    weight_kernel<<<WSIZE_ / 256, 256>>>(z, base_w, head_w, head_b);
    conv_kernel<<<dim3(32, 16), 256, SM_FLOATS * 4>>>(x, out);
}

// round 10
// speedup vs baseline: 1.1306x; 1.1306x over previous
#include <cuda_runtime.h>
#include <cstdint>

#define IC_   128
#define OC_   128
#define ZDIM_ 256
#define B_    16
#define WSIZE_ (OC_ * IC_ * 9)   // 147456

// Per-sample weights in m16n8k8 A-fragment order:
// [b][chunk j=icc*9+tap (36)][m16-tile (8)][ks (4)][lane (32)][reg (4)]
// lane = (m16&7)*4 + (k8&3); reg = (m16>>3) + 2*(k8>>2)
__device__ float g_w[(size_t)B_ * WSIZE_];

__device__ __forceinline__ float to_tf32(float v) {
    float o;
    asm("cvt.rna.tf32.f32 %0, %1;" : "=f"(o) : "f"(v));
    return o;
}

__device__ __forceinline__ uint32_t smem_u32(const void* p) {
    uint32_t a;
    asm("{ .reg .u64 t; cvta.to.shared.u64 t, %1; cvt.u32.u64 %0, t; }" : "=r"(a) : "l"(p));
    return a;
}

__device__ __forceinline__ void cp_async16(uint32_t dst, const void* src) {
    asm volatile("cp.async.cg.shared.global [%0], [%1], 16;" :: "r"(dst), "l"(src));
}

__device__ __forceinline__ void mma_tf32(float* d, const uint32_t* a,
                                         uint32_t b0, uint32_t b1) {
    asm volatile(
        "mma.sync.aligned.m16n8k8.row.col.f32.tf32.tf32.f32 "
        "{%0,%1,%2,%3}, {%4,%5,%6,%7}, {%8,%9}, {%0,%1,%2,%3};"
        : "+f"(d[0]), "+f"(d[1]), "+f"(d[2]), "+f"(d[3])
        : "r"(a[0]), "r"(a[1]), "r"(a[2]), "r"(a[3]), "r"(b0), "r"(b1));
}

// ---------------------------------------------------------------------------
// Kernel 1: per-sample weight generation on HMMA (single-pass tf32).
// D[m,b] = head_w[m,:] . z[b,:]; then + base_w[m] + head_b[m], tf32-rounded,
// scattered to fragment-order g_w.
// CTA: 128 rows (8 warps x m16), K=256 in 8 iters of 32.
// A: cp.async 3-stage ring (pitch 36 -> conflict-free frag LDS).
// B: z tf32-rounded once into SMEM [k][b] pitch 24 (conflict-free).
// SMEM floats: zs 6144, A 3*4608 = 13824. Total 19968 (78 KB dynamic).
// ---------------------------------------------------------------------------
#define WK_ZS_FLOATS (ZDIM_ * 24)
#define WK_A_FLOATS  (128 * 36)
#define WK_SM_FLOATS (WK_ZS_FLOATS + 3 * WK_A_FLOATS)

__global__ __launch_bounds__(256, 2) void weight_kernel(
    const float* __restrict__ z, const float* __restrict__ base_w,
    const float* __restrict__ head_w, const float* __restrict__ head_b)
{
    extern __shared__ float wsm[];
    float* zs = wsm;                 // [256 k][24 pitch] (b in 0..15)
    float* As = wsm + WK_ZS_FLOATS;  // 3 stages of [128 m][36 pitch]
    const uint32_t smbA = smem_u32(As);

    const int tid  = threadIdx.x;
    const int wid  = tid >> 5;
    const int lid  = tid & 31;
    const int g    = lid >> 2;       // 0..7
    const int tg   = lid & 3;        // 0..3
    const int mblk = blockIdx.x * 128;

    // A tile async copy: 128 rows x 32 k, pitch 36
    auto cpA = [&](int kit, int stage) {
        const float* src = head_w + (size_t)mblk * ZDIM_ + kit * 32;
        uint32_t dst = smbA + stage * (WK_A_FLOATS * 4);
#pragma unroll
        for (int p = 0; p < 4; p++) {
            int i   = tid + 256 * p;     // 0..1023
            int row = i >> 3;
            int c4  = i & 7;
            cp_async16(dst + (row * 36 + c4 * 4) * 4, src + row * ZDIM_ + c4 * 4);
        }
        asm volatile("cp.async.commit_group;" ::: "memory");
    };

    cpA(0, 0);
    cpA(1, 1);

    // z -> zs, tf32-rounded, [k][b] pitch 24
    for (int i = tid; i < B_ * ZDIM_; i += 256) {
        int b = i >> 8;
        int d = i & 255;
        zs[d * 24 + b] = to_tf32(z[i]);
    }

    float acc[2][4];
#pragma unroll
    for (int nt = 0; nt < 2; nt++)
#pragma unroll
        for (int r = 0; r < 4; r++) acc[nt][r] = 0.f;

    for (int kit = 0; kit < 8; kit++) {
        if (kit + 2 < 8) cpA(kit + 2, (kit + 2) % 3);

        if (kit <= 5)
            asm volatile("cp.async.wait_group 2;" ::: "memory");
        else if (kit == 6)
            asm volatile("cp.async.wait_group 1;" ::: "memory");
        else
            asm volatile("cp.async.wait_group 0;" ::: "memory");
        __syncthreads();

        const float* Aw = As + (kit % 3) * WK_A_FLOATS + (wid * 16) * 36;
#pragma unroll
        for (int ks = 0; ks < 4; ks++) {
            const int kl = ks * 8;
            uint32_t a[4];
            a[0] = __float_as_uint(to_tf32(Aw[g * 36 + kl + tg]));
            a[1] = __float_as_uint(to_tf32(Aw[(g + 8) * 36 + kl + tg]));
            a[2] = __float_as_uint(to_tf32(Aw[g * 36 + kl + tg + 4]));
            a[3] = __float_as_uint(to_tf32(Aw[(g + 8) * 36 + kl + tg + 4]));
            const int kg = kit * 32 + kl;
#pragma unroll
            for (int nt = 0; nt < 2; nt++) {
                uint32_t b0 = __float_as_uint(zs[(kg + tg) * 24 + g + 8 * nt]);
                uint32_t b1 = __float_as_uint(zs[(kg + tg + 4) * 24 + g + 8 * nt]);
                mma_tf32(acc[nt], a, b0, b1);
            }
        }
        __syncthreads();   // all warps done reading stage (kit%3) before reuse
    }

    // epilogue: add bias, scatter to fragment-order g_w
#pragma unroll
    for (int r = 0; r < 2; r++) {
        int m   = mblk + wid * 16 + g + r * 8;
        int oc  = m / 1152;
        int rem = m - oc * 1152;
        int ic  = rem / 9;
        int tap = rem - ic * 9;
        float bb = base_w[m] + head_b[m];

        int jc   = (ic >> 5) * 9 + tap;
        int k    = ic & 31;
        int ks   = k >> 3;
        int k8   = k & 7;
        int tile = oc >> 4;
        int m16  = oc & 15;
        int lane = (m16 & 7) * 4 + (k8 & 3);
        int reg  = (m16 >> 3) + 2 * (k8 >> 2);
        size_t off = (size_t)jc * 4096 + tile * 512 + ks * 128 + lane * 4 + reg;
#pragma unroll
        for (int nt = 0; nt < 2; nt++)
#pragma unroll
            for (int c = 0; c < 2; c++) {
                int b = 2 * tg + c + 8 * nt;
                float v = to_tf32(bb + acc[nt][r * 2 + c]);
                g_w[((size_t)b * 36) * 4096 + off] = v;
            }
    }
}

// ---------------------------------------------------------------------------
// Kernel 2: implicit-GEMM conv on mma.sync tf32 (HMMA).  [R8, best: 129.6us]
// CTA tile: M=128 oc x N=128 px (2 rows x 64 cols) x K=1152 (36 chunks of 32).
// 8 warps 4x2: each 32 oc x 64 px.
// A: per-warp PRIVATE 2-stage cp.async buffer, wait_group-paced, no barriers
//    inside icc groups.
// B: direct from xs slab (tf32-rounded x), ic-stride 280 -> conflict-free.
// SMEM floats: A private 8*2*1024 = 16384, xs at 16384 (8960). 99KB dynamic.
// ---------------------------------------------------------------------------
#define XS_OFF    16384
#define SM_FLOATS (16384 + 32 * 280)

__global__ __launch_bounds__(256, 2) void conv_kernel(
    const float* __restrict__ x, float* __restrict__ out)
{
    extern __shared__ float sm[];
    float* xs = sm + XS_OFF;
    const uint32_t smb = smem_u32(sm);

    const int tid  = threadIdx.x;
    const int wid  = tid >> 5;
    const int lid  = tid & 31;
    const int g    = lid >> 2;        // 0..7
    const int tg   = lid & 3;         // 0..3
    const int wm   = wid & 3;         // oc quarter (32 oc)
    const int wn   = wid >> 2;        // output row within pair
    const int pair = blockIdx.x;      // 0..31
    const int b    = blockIdx.y;      // 0..15
    const int r0   = pair * 2;

    const float* xb    = x + (size_t)b * IC_ * 4096;
    const float* wbase = g_w + ((size_t)b * 36) * 4096;

    float acc[2][8][4];
#pragma unroll
    for (int mt = 0; mt < 2; mt++)
#pragma unroll
        for (int nt = 0; nt < 8; nt++)
#pragma unroll
            for (int r = 0; r < 4; r++) acc[mt][nt][r] = 0.f;

    auto build_xs = [&](int icc) {
        for (int idx = tid; idx < 32 * 4 * 66; idx += 256) {
            int ic  = idx / 264;
            int rem = idx - ic * 264;
            int rr  = rem / 66;
            int cc  = rem - rr * 66;
            int gr  = r0 - 1 + rr;
            int gc  = cc - 1;
            float v = 0.f;
            if ((unsigned)gr < 64u && (unsigned)gc < 64u)
                v = xb[(size_t)(icc * 32 + ic) * 4096 + gr * 64 + gc];
            xs[ic * 280 + rr * 68 + cc] = to_tf32(v);
        }
    };

    // per-warp private A copy: this warp's 1024 fragment floats of chunk j
    const uint32_t aw_dst0 = smb + (wid * 2048 + lid * 4) * 4;
    auto cpA = [&](int j) {
        const float* src = wbase + (size_t)j * 4096 + wm * 1024 + lid * 4;
        uint32_t dst = aw_dst0 + (j & 1) * 4096;
#pragma unroll
        for (int i = 0; i < 8; i++)
            cp_async16(dst + i * 512, src + i * 128);
        asm volatile("cp.async.commit_group;" ::: "memory");
    };

    auto mma_chunk = [&](int stage, int kh, int kw) {
        const float* As = sm + wid * 2048 + stage * 1024 + lid * 4;
        const float* xw = xs + (wn + kh) * 68 + kw + g;
#pragma unroll
        for (int ks = 0; ks < 4; ks++) {
            float4 fa0 = *reinterpret_cast<const float4*>(As + ks * 128);
            float4 fa1 = *reinterpret_cast<const float4*>(As + 512 + ks * 128);
            uint32_t a0[4], a1[4];
            a0[0] = __float_as_uint(fa0.x); a0[1] = __float_as_uint(fa0.y);
            a0[2] = __float_as_uint(fa0.z); a0[3] = __float_as_uint(fa0.w);
            a1[0] = __float_as_uint(fa1.x); a1[1] = __float_as_uint(fa1.y);
            a1[2] = __float_as_uint(fa1.z); a1[3] = __float_as_uint(fa1.w);
            const int k0 = ks * 8 + tg;
            const float* xk0 = xw + k0 * 280;
            const float* xk1 = xk0 + 4 * 280;
#pragma unroll
            for (int nt = 0; nt < 8; nt++) {
                uint32_t b0 = __float_as_uint(xk0[nt * 8]);
                uint32_t b1 = __float_as_uint(xk1[nt * 8]);
                mma_tf32(acc[0][nt], a0, b0, b1);
                mma_tf32(acc[1][nt], a1, b0, b1);
            }
        }
    };

    // ---- prologue ----
    cpA(0);
    cpA(1);
    build_xs(0);
    __syncthreads();

    // ---- main loop: NO CTA barriers inside icc groups ----
    for (int icc = 0; icc < 4; icc++) {
#pragma unroll
        for (int tap = 0; tap < 9; tap++) {
            const int j  = icc * 9 + tap;
            const int kh = tap / 3;
            const int kw = tap - kh * 3;

            if (j < 34)
                asm volatile("cp.async.wait_group 1;" ::: "memory");
            else
                asm volatile("cp.async.wait_group 0;" ::: "memory");

            mma_chunk(j & 1, kh, kw);

            if (j + 2 < 36) cpA(j + 2);
        }
        if (icc < 3) {
            __syncthreads();          // all warps done reading xs
            build_xs(icc + 1);
            __syncthreads();
        }
    }

    // ---- epilogue: acc -> out[b][oc][px] ----
#pragma unroll
    for (int mt = 0; mt < 2; mt++) {
        int oc = wm * 32 + mt * 16 + g;
#pragma unroll
        for (int nt = 0; nt < 8; nt++) {
            int n  = wn * 64 + nt * 8 + 2 * tg;
            size_t base = ((size_t)b * OC_ + oc) * 4096 + pair * 128 + n;
            float2 v0 = make_float2(acc[mt][nt][0], acc[mt][nt][1]);
            float2 v1 = make_float2(acc[mt][nt][2], acc[mt][nt][3]);
            *reinterpret_cast<float2*>(out + base)            = v0;
            *reinterpret_cast<float2*>(out + base + 8 * 4096) = v1;
        }
    }
}

// ---------------------------------------------------------------------------
extern "C" void kernel_launch(void* const* d_in, const int* in_sizes, int n_in,
                              void* d_out, int out_size) {
    const float* x      = (const float*)d_in[0];
    const float* z      = (const float*)d_in[1];
    const float* base_w = (const float*)d_in[2];
    const float* head_w = (const float*)d_in[3];
    const float* head_b = (const float*)d_in[4];
    float* out = (float*)d_out;

    static bool attr_set = false;
    if (!attr_set) {
        cudaFuncSetAttribute(conv_kernel,
                             cudaFuncAttributeMaxDynamicSharedMemorySize,
                             SM_FLOATS * 4);
        cudaFuncSetAttribute(weight_kernel,
                             cudaFuncAttributeMaxDynamicSharedMemorySize,
                             WK_SM_FLOATS * 4);
        attr_set = true;
    }

    weight_kernel<<<WSIZE_ / 128, 256, WK_SM_FLOATS * 4>>>(z, base_w, head_w, head_b);
    conv_kernel<<<dim3(32, 16), 256, SM_FLOATS * 4>>>(x, out);
}

// round 11
// speedup vs baseline: 1.1414x; 1.0096x over previous
#include <cuda_runtime.h>
#include <cstdint>

#define IC_   128
#define OC_   128
#define ZDIM_ 256
#define B_    16
#define WSIZE_ (OC_ * IC_ * 9)   // 147456

// Per-sample weights in m16n8k8 A-fragment order:
// [b][chunk j=icc*9+tap (36)][m16-tile (8)][ks (4)][lane (32)][reg (4)]
// lane = (m16&7)*4 + (k8&3); reg = (m16>>3) + 2*(k8>>2)
__device__ float g_w[(size_t)B_ * WSIZE_];

__device__ __forceinline__ float to_tf32(float v) {
    float o;
    asm("cvt.rna.tf32.f32 %0, %1;" : "=f"(o) : "f"(v));
    return o;
}

__device__ __forceinline__ uint32_t smem_u32(const void* p) {
    uint32_t a;
    asm("{ .reg .u64 t; cvta.to.shared.u64 t, %1; cvt.u32.u64 %0, t; }" : "=r"(a) : "l"(p));
    return a;
}

__device__ __forceinline__ void cp_async16(uint32_t dst, const void* src) {
    asm volatile("cp.async.cg.shared.global [%0], [%1], 16;" :: "r"(dst), "l"(src));
}

__device__ __forceinline__ void mma_tf32(float* d, const uint32_t* a,
                                         uint32_t b0, uint32_t b1) {
    asm volatile(
        "mma.sync.aligned.m16n8k8.row.col.f32.tf32.tf32.f32 "
        "{%0,%1,%2,%3}, {%4,%5,%6,%7}, {%8,%9}, {%0,%1,%2,%3};"
        : "+f"(d[0]), "+f"(d[1]), "+f"(d[2]), "+f"(d[3])
        : "r"(a[0]), "r"(a[1]), "r"(a[2]), "r"(a[3]), "r"(b0), "r"(b1));
}

// ---------------------------------------------------------------------------
// Kernel 1: per-sample weight generation on HMMA (single-pass tf32).
// D[m,b] = head_w[m,:] . z[b,:] + base_w[m] + head_b[m] -> fragment-order g_w.
// CTA: 128 rows (8 warps x 16 rows), K=256 in 8 iters of 32.
// A: WARP-PRIVATE 2-stage cp.async ring (pitch 36 -> conflict-free frag LDS),
//    per-warp wait_group pacing, NO CTA barriers in the k-loop.
// B: z tf32-rounded once into SMEM [k][b] pitch 24 (conflict-free).
// SMEM floats: zs 6144, A private 8*2*576 = 9216. Total 15360 (60 KB).
// ---------------------------------------------------------------------------
#define WK_ZS_FLOATS (ZDIM_ * 24)
#define WK_AST_FLOATS 576                 // one stage: 16 rows x 36 pitch
#define WK_SM_FLOATS (WK_ZS_FLOATS + 8 * 2 * WK_AST_FLOATS)

__global__ __launch_bounds__(256, 3) void weight_kernel(
    const float* __restrict__ z, const float* __restrict__ base_w,
    const float* __restrict__ head_w, const float* __restrict__ head_b)
{
    extern __shared__ float wsm[];
    float* zs = wsm;                                  // [256 k][24 pitch]
    float* Aw0 = wsm + WK_ZS_FLOATS;                  // warp stages

    const int tid  = threadIdx.x;
    const int wid  = tid >> 5;
    const int lid  = tid & 31;
    const int g    = lid >> 2;       // 0..7
    const int tg   = lid & 3;        // 0..3
    const int mblk = blockIdx.x * 128;

    float* Awarp = Aw0 + wid * (2 * WK_AST_FLOATS);
    const uint32_t AwarpB = smem_u32(Awarp);
    const float* rows = head_w + (size_t)(mblk + wid * 16) * ZDIM_;

    // per-warp A copy: 16 rows x 32 k of this warp's rows, 4 LDGSTS per lane
    auto cpA = [&](int kit, int stage) {
        uint32_t dstb = AwarpB + stage * (WK_AST_FLOATS * 4);
#pragma unroll
        for (int p = 0; p < 4; p++) {
            int idx = lid + 32 * p;          // 0..127 float4 slots
            int row = idx >> 3;              // 0..15
            int c4  = idx & 7;               // 0..7
            cp_async16(dstb + (row * 36 + c4 * 4) * 4,
                       rows + (size_t)row * ZDIM_ + kit * 32 + c4 * 4);
        }
        asm volatile("cp.async.commit_group;" ::: "memory");
    };

    cpA(0, 0);
    cpA(1, 1);

    // z -> zs, tf32-rounded, [k][b] pitch 24
    for (int i = tid; i < B_ * ZDIM_; i += 256) {
        int b = i >> 8;
        int d = i & 255;
        zs[d * 24 + b] = to_tf32(z[i]);
    }

    float acc[2][4];
#pragma unroll
    for (int nt = 0; nt < 2; nt++)
#pragma unroll
        for (int r = 0; r < 4; r++) acc[nt][r] = 0.f;

    __syncthreads();   // zs visible to all (A stages are warp-private)

    for (int kit = 0; kit < 8; kit++) {
        if (kit < 7)
            asm volatile("cp.async.wait_group 1;" ::: "memory");
        else
            asm volatile("cp.async.wait_group 0;" ::: "memory");

        const float* As = Awarp + (kit & 1) * WK_AST_FLOATS;
#pragma unroll
        for (int ks = 0; ks < 4; ks++) {
            const int kl = ks * 8;
            uint32_t a[4];
            a[0] = __float_as_uint(to_tf32(As[g * 36 + kl + tg]));
            a[1] = __float_as_uint(to_tf32(As[(g + 8) * 36 + kl + tg]));
            a[2] = __float_as_uint(to_tf32(As[g * 36 + kl + tg + 4]));
            a[3] = __float_as_uint(to_tf32(As[(g + 8) * 36 + kl + tg + 4]));
            const int kg = kit * 32 + kl;
#pragma unroll
            for (int nt = 0; nt < 2; nt++) {
                uint32_t b0 = __float_as_uint(zs[(kg + tg) * 24 + g + 8 * nt]);
                uint32_t b1 = __float_as_uint(zs[(kg + tg + 4) * 24 + g + 8 * nt]);
                mma_tf32(acc[nt], a, b0, b1);
            }
        }

        if (kit + 2 < 8) cpA(kit + 2, kit & 1);   // stage (kit+2)&1 == kit&1, read done
    }

    // epilogue: add bias, scatter to fragment-order g_w
#pragma unroll
    for (int r = 0; r < 2; r++) {
        int m   = mblk + wid * 16 + g + r * 8;
        int oc  = m / 1152;
        int rem = m - oc * 1152;
        int ic  = rem / 9;
        int tap = rem - ic * 9;
        float bb = base_w[m] + head_b[m];

        int jc   = (ic >> 5) * 9 + tap;
        int k    = ic & 31;
        int ks   = k >> 3;
        int k8   = k & 7;
        int tile = oc >> 4;
        int m16  = oc & 15;
        int lane = (m16 & 7) * 4 + (k8 & 3);
        int reg  = (m16 >> 3) + 2 * (k8 >> 2);
        size_t off = (size_t)jc * 4096 + tile * 512 + ks * 128 + lane * 4 + reg;
#pragma unroll
        for (int nt = 0; nt < 2; nt++)
#pragma unroll
            for (int c = 0; c < 2; c++) {
                int b = 2 * tg + c + 8 * nt;
                float v = to_tf32(bb + acc[nt][r * 2 + c]);
                g_w[((size_t)b * 36) * 4096 + off] = v;
            }
    }
}

// ---------------------------------------------------------------------------
// Kernel 2: implicit-GEMM conv on mma.sync tf32 (HMMA).  [R8, best: ~130us]
// CTA tile: M=128 oc x N=128 px (2 rows x 64 cols) x K=1152 (36 chunks of 32).
// 8 warps 4x2: each 32 oc x 64 px.
// A: per-warp PRIVATE 2-stage cp.async buffer, wait_group-paced, no barriers
//    inside icc groups.
// B: direct from xs slab (tf32-rounded x), ic-stride 280 -> conflict-free.
// SMEM floats: A private 8*2*1024 = 16384, xs at 16384 (8960). 99KB dynamic.
// ---------------------------------------------------------------------------
#define XS_OFF    16384
#define SM_FLOATS (16384 + 32 * 280)

__global__ __launch_bounds__(256, 2) void conv_kernel(
    const float* __restrict__ x, float* __restrict__ out)
{
    extern __shared__ float sm[];
    float* xs = sm + XS_OFF;
    const uint32_t smb = smem_u32(sm);

    const int tid  = threadIdx.x;
    const int wid  = tid >> 5;
    const int lid  = tid & 31;
    const int g    = lid >> 2;        // 0..7
    const int tg   = lid & 3;         // 0..3
    const int wm   = wid & 3;         // oc quarter (32 oc)
    const int wn   = wid >> 2;        // output row within pair
    const int pair = blockIdx.x;      // 0..31
    const int b    = blockIdx.y;      // 0..15
    const int r0   = pair * 2;

    const float* xb    = x + (size_t)b * IC_ * 4096;
    const float* wbase = g_w + ((size_t)b * 36) * 4096;

    float acc[2][8][4];
#pragma unroll
    for (int mt = 0; mt < 2; mt++)
#pragma unroll
        for (int nt = 0; nt < 8; nt++)
#pragma unroll
            for (int r = 0; r < 4; r++) acc[mt][nt][r] = 0.f;

    auto build_xs = [&](int icc) {
        for (int idx = tid; idx < 32 * 4 * 66; idx += 256) {
            int ic  = idx / 264;
            int rem = idx - ic * 264;
            int rr  = rem / 66;
            int cc  = rem - rr * 66;
            int gr  = r0 - 1 + rr;
            int gc  = cc - 1;
            float v = 0.f;
            if ((unsigned)gr < 64u && (unsigned)gc < 64u)
                v = xb[(size_t)(icc * 32 + ic) * 4096 + gr * 64 + gc];
            xs[ic * 280 + rr * 68 + cc] = to_tf32(v);
        }
    };

    // per-warp private A copy: this warp's 1024 fragment floats of chunk j
    const uint32_t aw_dst0 = smb + (wid * 2048 + lid * 4) * 4;
    auto cpA = [&](int j) {
        const float* src = wbase + (size_t)j * 4096 + wm * 1024 + lid * 4;
        uint32_t dst = aw_dst0 + (j & 1) * 4096;
#pragma unroll
        for (int i = 0; i < 8; i++)
            cp_async16(dst + i * 512, src + i * 128);
        asm volatile("cp.async.commit_group;" ::: "memory");
    };

    auto mma_chunk = [&](int stage, int kh, int kw) {
        const float* As = sm + wid * 2048 + stage * 1024 + lid * 4;
        const float* xw = xs + (wn + kh) * 68 + kw + g;
#pragma unroll
        for (int ks = 0; ks < 4; ks++) {
            float4 fa0 = *reinterpret_cast<const float4*>(As + ks * 128);
            float4 fa1 = *reinterpret_cast<const float4*>(As + 512 + ks * 128);
            uint32_t a0[4], a1[4];
            a0[0] = __float_as_uint(fa0.x); a0[1] = __float_as_uint(fa0.y);
            a0[2] = __float_as_uint(fa0.z); a0[3] = __float_as_uint(fa0.w);
            a1[0] = __float_as_uint(fa1.x); a1[1] = __float_as_uint(fa1.y);
            a1[2] = __float_as_uint(fa1.z); a1[3] = __float_as_uint(fa1.w);
            const int k0 = ks * 8 + tg;
            const float* xk0 = xw + k0 * 280;
            const float* xk1 = xk0 + 4 * 280;
#pragma unroll
            for (int nt = 0; nt < 8; nt++) {
                uint32_t b0 = __float_as_uint(xk0[nt * 8]);
                uint32_t b1 = __float_as_uint(xk1[nt * 8]);
                mma_tf32(acc[0][nt], a0, b0, b1);
                mma_tf32(acc[1][nt], a1, b0, b1);
            }
        }
    };

    // ---- prologue ----
    cpA(0);
    cpA(1);
    build_xs(0);
    __syncthreads();

    // ---- main loop: NO CTA barriers inside icc groups ----
    for (int icc = 0; icc < 4; icc++) {
#pragma unroll
        for (int tap = 0; tap < 9; tap++) {
            const int j  = icc * 9 + tap;
            const int kh = tap / 3;
            const int kw = tap - kh * 3;

            if (j < 34)
                asm volatile("cp.async.wait_group 1;" ::: "memory");
            else
                asm volatile("cp.async.wait_group 0;" ::: "memory");

            mma_chunk(j & 1, kh, kw);

            if (j + 2 < 36) cpA(j + 2);
        }
        if (icc < 3) {
            __syncthreads();          // all warps done reading xs
            build_xs(icc + 1);
            __syncthreads();
        }
    }

    // ---- epilogue: acc -> out[b][oc][px] ----
#pragma unroll
    for (int mt = 0; mt < 2; mt++) {
        int oc = wm * 32 + mt * 16 + g;
#pragma unroll
        for (int nt = 0; nt < 8; nt++) {
            int n  = wn * 64 + nt * 8 + 2 * tg;
            size_t base = ((size_t)b * OC_ + oc) * 4096 + pair * 128 + n;
            float2 v0 = make_float2(acc[mt][nt][0], acc[mt][nt][1]);
            float2 v1 = make_float2(acc[mt][nt][2], acc[mt][nt][3]);
            *reinterpret_cast<float2*>(out + base)            = v0;
            *reinterpret_cast<float2*>(out + base + 8 * 4096) = v1;
        }
    }
}

// ---------------------------------------------------------------------------
extern "C" void kernel_launch(void* const* d_in, const int* in_sizes, int n_in,
                              void* d_out, int out_size) {
    const float* x      = (const float*)d_in[0];
    const float* z      = (const float*)d_in[1];
    const float* base_w = (const float*)d_in[2];
    const float* head_w = (const float*)d_in[3];
    const float* head_b = (const float*)d_in[4];
    float* out = (float*)d_out;

    static bool attr_set = false;
    if (!attr_set) {
        cudaFuncSetAttribute(conv_kernel,
                             cudaFuncAttributeMaxDynamicSharedMemorySize,
                             SM_FLOATS * 4);
        cudaFuncSetAttribute(weight_kernel,
                             cudaFuncAttributeMaxDynamicSharedMemorySize,
                             WK_SM_FLOATS * 4);
        attr_set = true;
    }

    weight_kernel<<<WSIZE_ / 128, 256, WK_SM_FLOATS * 4>>>(z, base_w, head_w, head_b);
    conv_kernel<<<dim3(32, 16), 256, SM_FLOATS * 4>>>(x, out);
}

// round 12
// speedup vs baseline: 1.1809x; 1.0345x over previous
#include <cuda_runtime.h>
#include <cstdint>

#define IC_   128
#define OC_   128
#define ZDIM_ 256
#define B_    16
#define WSIZE_ (OC_ * IC_ * 9)   // 147456

// Per-sample weights in m16n8k8 A-fragment order:
// [b][chunk j=icc*9+tap (36)][m16-tile (8)][ks (4)][lane (32)][reg (4)]
// lane = (m16&7)*4 + (k8&3); reg = (m16>>3) + 2*(k8>>2)
__device__ float g_w[(size_t)B_ * WSIZE_];

__device__ __forceinline__ float to_tf32(float v) {
    float o;
    asm("cvt.rna.tf32.f32 %0, %1;" : "=f"(o) : "f"(v));
    return o;
}

__device__ __forceinline__ uint32_t smem_u32(const void* p) {
    uint32_t a;
    asm("{ .reg .u64 t; cvta.to.shared.u64 t, %1; cvt.u32.u64 %0, t; }" : "=r"(a) : "l"(p));
    return a;
}

__device__ __forceinline__ void cp_async16(uint32_t dst, const void* src) {
    asm volatile("cp.async.cg.shared.global [%0], [%1], 16;" :: "r"(dst), "l"(src));
}

__device__ __forceinline__ void mma_tf32(float* d, const uint32_t* a,
                                         uint32_t b0, uint32_t b1) {
    asm volatile(
        "mma.sync.aligned.m16n8k8.row.col.f32.tf32.tf32.f32 "
        "{%0,%1,%2,%3}, {%4,%5,%6,%7}, {%8,%9}, {%0,%1,%2,%3};"
        : "+f"(d[0]), "+f"(d[1]), "+f"(d[2]), "+f"(d[3])
        : "r"(a[0]), "r"(a[1]), "r"(a[2]), "r"(a[3]), "r"(b0), "r"(b1));
}

// ---------------------------------------------------------------------------
// Kernel 1: per-sample weight generation on HMMA (single-pass tf32).
// CTA owns ONE contiguous 128-float g_w segment per b: (tile, icc, ks, tap)
// fixed; rows = 16 oc (m16) x 8 ic (k8 = warp id). Warp w computes m16=0..15
// at k8=w over K=256 (8 kits of 32), warp-private 2-stage cp.async A ring.
// Reads: coalesced 128B row chunks. Writes: SMEM transpose -> float4-coalesced
// 512B segments (9.4MB instead of ~75MB of scattered-store sectors).
// SMEM floats: zs 6144, A private 8*2*576 = 9216 (reused as 2048-fl outbuf).
// ---------------------------------------------------------------------------
#define WK_ZS_FLOATS (ZDIM_ * 24)
#define WK_AST_FLOATS 576                 // one stage: 16 rows x 36 pitch
#define WK_SM_FLOATS (WK_ZS_FLOATS + 8 * 2 * WK_AST_FLOATS)

__global__ __launch_bounds__(256, 3) void weight_kernel(
    const float* __restrict__ z, const float* __restrict__ base_w,
    const float* __restrict__ head_w, const float* __restrict__ head_b)
{
    extern __shared__ float wsm[];
    float* zs  = wsm;                                 // [256 k][24 pitch]
    float* Aw0 = wsm + WK_ZS_FLOATS;                  // warp A stages / outbuf

    const int tid = threadIdx.x;
    const int wid = tid >> 5;        // = k8 for this warp
    const int lid = tid & 31;
    const int g   = lid >> 2;        // 0..7
    const int tg  = lid & 3;         // 0..3

    // decompose block id: bid = ((tile*4 + icc)*4 + ks)*9 + tap
    const int bid  = blockIdx.x;
    const int tap  = bid % 9;
    const int t2   = bid / 9;
    const int ks_  = t2 & 3;
    const int icc  = (t2 >> 2) & 3;
    const int tile = t2 >> 4;        // 0..7

    // row m for fragment row m16: m = m0 + m16*1152
    const int m0 = (tile * 16) * 1152 + (icc * 32 + ks_ * 8 + wid) * 9 + tap;

    float* Awarp = Aw0 + wid * (2 * WK_AST_FLOATS);
    const uint32_t AwarpB = smem_u32(Awarp);

    // per-warp A copy: 16 rows (m16) x 32 k, rows strided 1152 apart in head_w
    auto cpA = [&](int kit, int stage) {
        uint32_t dstb = AwarpB + stage * (WK_AST_FLOATS * 4);
        const int c4 = lid & 7;
#pragma unroll
        for (int p = 0; p < 4; p++) {
            int row = (lid >> 3) + 4 * p;    // m16 0..15
            cp_async16(dstb + (row * 36 + c4 * 4) * 4,
                       head_w + (size_t)(m0 + row * 1152) * ZDIM_ + kit * 32 + c4 * 4);
        }
        asm volatile("cp.async.commit_group;" ::: "memory");
    };

    cpA(0, 0);
    cpA(1, 1);

    // z -> zs, tf32-rounded, [k][b] pitch 24
    for (int i = tid; i < B_ * ZDIM_; i += 256) {
        int b = i >> 8;
        int d = i & 255;
        zs[d * 24 + b] = to_tf32(z[i]);
    }

    float acc[2][4];
#pragma unroll
    for (int nt = 0; nt < 2; nt++)
#pragma unroll
        for (int r = 0; r < 4; r++) acc[nt][r] = 0.f;

    __syncthreads();   // zs visible (A stages are warp-private)

    for (int kit = 0; kit < 8; kit++) {
        if (kit < 7)
            asm volatile("cp.async.wait_group 1;" ::: "memory");
        else
            asm volatile("cp.async.wait_group 0;" ::: "memory");

        const float* As = Awarp + (kit & 1) * WK_AST_FLOATS;
#pragma unroll
        for (int ks = 0; ks < 4; ks++) {
            const int kl = ks * 8;
            uint32_t a[4];
            a[0] = __float_as_uint(to_tf32(As[g * 36 + kl + tg]));
            a[1] = __float_as_uint(to_tf32(As[(g + 8) * 36 + kl + tg]));
            a[2] = __float_as_uint(to_tf32(As[g * 36 + kl + tg + 4]));
            a[3] = __float_as_uint(to_tf32(As[(g + 8) * 36 + kl + tg + 4]));
            const int kg = kit * 32 + kl;
#pragma unroll
            for (int nt = 0; nt < 2; nt++) {
                uint32_t b0 = __float_as_uint(zs[(kg + tg) * 24 + g + 8 * nt]);
                uint32_t b1 = __float_as_uint(zs[(kg + tg + 4) * 24 + g + 8 * nt]);
                mma_tf32(acc[nt], a, b0, b1);
            }
        }

        if (kit + 2 < 8) cpA(kit + 2, kit & 1);
    }

    // bias per fragment row
    float bb[2];
#pragma unroll
    for (int r = 0; r < 2; r++) {
        int m = m0 + (g + 8 * r) * 1152;
        bb[r] = base_w[m] + head_b[m];
    }

    __syncthreads();                 // all warps done reading A stages
    float* ob = Aw0;                 // outbuf [b][128]

    // off = lane*4+reg = 16*g + 4*(wid&3) + r + 2*(wid>>2)   (m16 = g+8r)
    const int offb = 16 * g + 4 * (wid & 3) + 2 * (wid >> 2);
#pragma unroll
    for (int nt = 0; nt < 2; nt++)
#pragma unroll
        for (int r = 0; r < 2; r++)
#pragma unroll
            for (int c = 0; c < 2; c++) {
                int b = 2 * tg + c + 8 * nt;
                ob[b * 128 + offb + r] = to_tf32(bb[r] + acc[nt][r * 2 + c]);
            }
    __syncthreads();

    // coalesced write: 16 segments of 512B
    {
        const int b   = tid >> 4;
        const int seg = (tid & 15) * 8;
        const int jc  = icc * 9 + tap;
        float* dst = g_w + ((size_t)b * 36 + jc) * 4096 + tile * 512 + ks_ * 128 + seg;
        *reinterpret_cast<float4*>(dst)     = *reinterpret_cast<float4*>(&ob[b * 128 + seg]);
        *reinterpret_cast<float4*>(dst + 4) = *reinterpret_cast<float4*>(&ob[b * 128 + seg + 4]);
    }
}

// ---------------------------------------------------------------------------
// Kernel 2: implicit-GEMM conv on mma.sync tf32 (HMMA).  [R8, best: ~130us]
// CTA tile: M=128 oc x N=128 px (2 rows x 64 cols) x K=1152 (36 chunks of 32).
// 8 warps 4x2: each 32 oc x 64 px.
// A: per-warp PRIVATE 2-stage cp.async buffer, wait_group-paced, no barriers
//    inside icc groups.
// B: direct from xs slab (tf32-rounded x), ic-stride 280 -> conflict-free.
// SMEM floats: A private 8*2*1024 = 16384, xs at 16384 (8960). 99KB dynamic.
// ---------------------------------------------------------------------------
#define XS_OFF    16384
#define SM_FLOATS (16384 + 32 * 280)

__global__ __launch_bounds__(256, 2) void conv_kernel(
    const float* __restrict__ x, float* __restrict__ out)
{
    extern __shared__ float sm[];
    float* xs = sm + XS_OFF;
    const uint32_t smb = smem_u32(sm);

    const int tid  = threadIdx.x;
    const int wid  = tid >> 5;
    const int lid  = tid & 31;
    const int g    = lid >> 2;        // 0..7
    const int tg   = lid & 3;         // 0..3
    const int wm   = wid & 3;         // oc quarter (32 oc)
    const int wn   = wid >> 2;        // output row within pair
    const int pair = blockIdx.x;      // 0..31
    const int b    = blockIdx.y;      // 0..15
    const int r0   = pair * 2;

    const float* xb    = x + (size_t)b * IC_ * 4096;
    const float* wbase = g_w + ((size_t)b * 36) * 4096;

    float acc[2][8][4];
#pragma unroll
    for (int mt = 0; mt < 2; mt++)
#pragma unroll
        for (int nt = 0; nt < 8; nt++)
#pragma unroll
            for (int r = 0; r < 4; r++) acc[mt][nt][r] = 0.f;

    auto build_xs = [&](int icc) {
        for (int idx = tid; idx < 32 * 4 * 66; idx += 256) {
            int ic  = idx / 264;
            int rem = idx - ic * 264;
            int rr  = rem / 66;
            int cc  = rem - rr * 66;
            int gr  = r0 - 1 + rr;
            int gc  = cc - 1;
            float v = 0.f;
            if ((unsigned)gr < 64u && (unsigned)gc < 64u)
                v = xb[(size_t)(icc * 32 + ic) * 4096 + gr * 64 + gc];
            xs[ic * 280 + rr * 68 + cc] = to_tf32(v);
        }
    };

    // per-warp private A copy: this warp's 1024 fragment floats of chunk j
    const uint32_t aw_dst0 = smb + (wid * 2048 + lid * 4) * 4;
    auto cpA = [&](int j) {
        const float* src = wbase + (size_t)j * 4096 + wm * 1024 + lid * 4;
        uint32_t dst = aw_dst0 + (j & 1) * 4096;
#pragma unroll
        for (int i = 0; i < 8; i++)
            cp_async16(dst + i * 512, src + i * 128);
        asm volatile("cp.async.commit_group;" ::: "memory");
    };

    auto mma_chunk = [&](int stage, int kh, int kw) {
        const float* As = sm + wid * 2048 + stage * 1024 + lid * 4;
        const float* xw = xs + (wn + kh) * 68 + kw + g;
#pragma unroll
        for (int ks = 0; ks < 4; ks++) {
            float4 fa0 = *reinterpret_cast<const float4*>(As + ks * 128);
            float4 fa1 = *reinterpret_cast<const float4*>(As + 512 + ks * 128);
            uint32_t a0[4], a1[4];
            a0[0] = __float_as_uint(fa0.x); a0[1] = __float_as_uint(fa0.y);
            a0[2] = __float_as_uint(fa0.z); a0[3] = __float_as_uint(fa0.w);
            a1[0] = __float_as_uint(fa1.x); a1[1] = __float_as_uint(fa1.y);
            a1[2] = __float_as_uint(fa1.z); a1[3] = __float_as_uint(fa1.w);
            const int k0 = ks * 8 + tg;
            const float* xk0 = xw + k0 * 280;
            const float* xk1 = xk0 + 4 * 280;
#pragma unroll
            for (int nt = 0; nt < 8; nt++) {
                uint32_t b0 = __float_as_uint(xk0[nt * 8]);
                uint32_t b1 = __float_as_uint(xk1[nt * 8]);
                mma_tf32(acc[0][nt], a0, b0, b1);
                mma_tf32(acc[1][nt], a1, b0, b1);
            }
        }
    };

    // ---- prologue ----
    cpA(0);
    cpA(1);
    build_xs(0);
    __syncthreads();

    // ---- main loop: NO CTA barriers inside icc groups ----
    for (int icc = 0; icc < 4; icc++) {
#pragma unroll
        for (int tap = 0; tap < 9; tap++) {
            const int j  = icc * 9 + tap;
            const int kh = tap / 3;
            const int kw = tap - kh * 3;

            if (j < 34)
                asm volatile("cp.async.wait_group 1;" ::: "memory");
            else
                asm volatile("cp.async.wait_group 0;" ::: "memory");

            mma_chunk(j & 1, kh, kw);

            if (j + 2 < 36) cpA(j + 2);
        }
        if (icc < 3) {
            __syncthreads();          // all warps done reading xs
            build_xs(icc + 1);
            __syncthreads();
        }
    }

    // ---- epilogue: acc -> out[b][oc][px] ----
#pragma unroll
    for (int mt = 0; mt < 2; mt++) {
        int oc = wm * 32 + mt * 16 + g;
#pragma unroll
        for (int nt = 0; nt < 8; nt++) {
            int n  = wn * 64 + nt * 8 + 2 * tg;
            size_t base = ((size_t)b * OC_ + oc) * 4096 + pair * 128 + n;
            float2 v0 = make_float2(acc[mt][nt][0], acc[mt][nt][1]);
            float2 v1 = make_float2(acc[mt][nt][2], acc[mt][nt][3]);
            *reinterpret_cast<float2*>(out + base)            = v0;
            *reinterpret_cast<float2*>(out + base + 8 * 4096) = v1;
        }
    }
}

// ---------------------------------------------------------------------------
extern "C" void kernel_launch(void* const* d_in, const int* in_sizes, int n_in,
                              void* d_out, int out_size) {
    const float* x      = (const float*)d_in[0];
    const float* z      = (const float*)d_in[1];
    const float* base_w = (const float*)d_in[2];
    const float* head_w = (const float*)d_in[3];
    const float* head_b = (const float*)d_in[4];
    float* out = (float*)d_out;

    static bool attr_set = false;
    if (!attr_set) {
        cudaFuncSetAttribute(conv_kernel,
                             cudaFuncAttributeMaxDynamicSharedMemorySize,
                             SM_FLOATS * 4);
        cudaFuncSetAttribute(weight_kernel,
                             cudaFuncAttributeMaxDynamicSharedMemorySize,
                             WK_SM_FLOATS * 4);
        attr_set = true;
    }

    weight_kernel<<<1152, 256, WK_SM_FLOATS * 4>>>(z, base_w, head_w, head_b);
    conv_kernel<<<dim3(32, 16), 256, SM_FLOATS * 4>>>(x, out);
}

// round 13
// speedup vs baseline: 1.5959x; 1.3515x over previous
#include <cuda_runtime.h>
#include <cuda_fp16.h>
#include <cstdint>

#define IC_   128
#define OC_   128
#define ZDIM_ 256
#define B_    16
#define WSIZE_ (OC_ * IC_ * 9)   // 147456

// Per-sample weights as fp16 in m16n8k16 A-fragment order:
// [b][chunk j=icc*9+tap (36)][tile (8)][kstep (2)][lane (32)][8 halves]
// half index = r_frag*2 + h; row = g + 8*(r&1); col(k16) = 2*tg + 8*(r>>1) + h
__device__ __half g_w[(size_t)B_ * WSIZE_];

__device__ __forceinline__ float to_tf32(float v) {
    float o;
    asm("cvt.rna.tf32.f32 %0, %1;" : "=f"(o) : "f"(v));
    return o;
}

__device__ __forceinline__ uint32_t smem_u32(const void* p) {
    uint32_t a;
    asm("{ .reg .u64 t; cvta.to.shared.u64 t, %1; cvt.u32.u64 %0, t; }" : "=r"(a) : "l"(p));
    return a;
}

__device__ __forceinline__ void cp_async16(uint32_t dst, const void* src) {
    asm volatile("cp.async.cg.shared.global [%0], [%1], 16;" :: "r"(dst), "l"(src));
}

__device__ __forceinline__ void mma_tf32(float* d, const uint32_t* a,
                                         uint32_t b0, uint32_t b1) {
    asm volatile(
        "mma.sync.aligned.m16n8k8.row.col.f32.tf32.tf32.f32 "
        "{%0,%1,%2,%3}, {%4,%5,%6,%7}, {%8,%9}, {%0,%1,%2,%3};"
        : "+f"(d[0]), "+f"(d[1]), "+f"(d[2]), "+f"(d[3])
        : "r"(a[0]), "r"(a[1]), "r"(a[2]), "r"(a[3]), "r"(b0), "r"(b1));
}

__device__ __forceinline__ void mma_f16(float* d, const uint32_t* a,
                                        uint32_t b0, uint32_t b1) {
    asm volatile(
        "mma.sync.aligned.m16n8k16.row.col.f32.f16.f16.f32 "
        "{%0,%1,%2,%3}, {%4,%5,%6,%7}, {%8,%9}, {%0,%1,%2,%3};"
        : "+f"(d[0]), "+f"(d[1]), "+f"(d[2]), "+f"(d[3])
        : "r"(a[0]), "r"(a[1]), "r"(a[2]), "r"(a[3]), "r"(b0), "r"(b1));
}

// ---------------------------------------------------------------------------
// Kernel 1: per-sample weight generation on HMMA tf32, fp16 fragment output.
// CTA = (tile, icc, kstep, ichalf, tap); warp w handles ic_local16 = ichalf*8+w,
// rows = 16 oc (m16). K=256 in 8 kits of 32, warp-private 2-stage cp.async.
// Epilogue: SMEM transpose -> coalesced 8B writes of fp16 fragment halves.
// ---------------------------------------------------------------------------
#define WK_ZS_FLOATS (ZDIM_ * 24)
#define WK_AST_FLOATS 576                 // one stage: 16 rows x 36 pitch
#define WK_SM_FLOATS (WK_ZS_FLOATS + 8 * 2 * WK_AST_FLOATS)

__global__ __launch_bounds__(256, 3) void weight_kernel(
    const float* __restrict__ z, const float* __restrict__ base_w,
    const float* __restrict__ head_w, const float* __restrict__ head_b)
{
    extern __shared__ float wsm[];
    float* zs  = wsm;                                 // [256 k][24 pitch]
    float* Aw0 = wsm + WK_ZS_FLOATS;                  // warp A stages / outbuf

    const int tid = threadIdx.x;
    const int wid = tid >> 5;
    const int lid = tid & 31;
    const int g   = lid >> 2;        // 0..7
    const int tg  = lid & 3;         // 0..3

    // bid = (((tile*4 + icc)*2 + kstep)*2 + ichalf)*9 + tap
    const int bid    = blockIdx.x;
    const int tap    = bid % 9;
    const int t      = bid / 9;
    const int ichalf = t & 1;
    const int kstep  = (t >> 1) & 1;
    const int icc    = (t >> 2) & 3;
    const int tile   = t >> 4;       // 0..7

    const int ic = icc * 32 + kstep * 16 + ichalf * 8 + wid;
    const int m0 = (tile * 16) * 1152 + ic * 9 + tap;

    float* Awarp = Aw0 + wid * (2 * WK_AST_FLOATS);
    const uint32_t AwarpB = smem_u32(Awarp);

    auto cpA = [&](int kit, int stage) {
        uint32_t dstb = AwarpB + stage * (WK_AST_FLOATS * 4);
        const int c4 = lid & 7;
#pragma unroll
        for (int p = 0; p < 4; p++) {
            int row = (lid >> 3) + 4 * p;    // m16 0..15
            cp_async16(dstb + (row * 36 + c4 * 4) * 4,
                       head_w + (size_t)(m0 + row * 1152) * ZDIM_ + kit * 32 + c4 * 4);
        }
        asm volatile("cp.async.commit_group;" ::: "memory");
    };

    cpA(0, 0);
    cpA(1, 1);

    for (int i = tid; i < B_ * ZDIM_; i += 256) {
        int b = i >> 8;
        int d = i & 255;
        zs[d * 24 + b] = to_tf32(z[i]);
    }

    float acc[2][4];
#pragma unroll
    for (int nt = 0; nt < 2; nt++)
#pragma unroll
        for (int r = 0; r < 4; r++) acc[nt][r] = 0.f;

    __syncthreads();

    for (int kit = 0; kit < 8; kit++) {
        if (kit < 7)
            asm volatile("cp.async.wait_group 1;" ::: "memory");
        else
            asm volatile("cp.async.wait_group 0;" ::: "memory");

        const float* As = Awarp + (kit & 1) * WK_AST_FLOATS;
#pragma unroll
        for (int ks = 0; ks < 4; ks++) {
            const int kl = ks * 8;
            uint32_t a[4];
            a[0] = __float_as_uint(to_tf32(As[g * 36 + kl + tg]));
            a[1] = __float_as_uint(to_tf32(As[(g + 8) * 36 + kl + tg]));
            a[2] = __float_as_uint(to_tf32(As[g * 36 + kl + tg + 4]));
            a[3] = __float_as_uint(to_tf32(As[(g + 8) * 36 + kl + tg + 4]));
            const int kg = kit * 32 + kl;
#pragma unroll
            for (int nt = 0; nt < 2; nt++) {
                uint32_t b0 = __float_as_uint(zs[(kg + tg) * 24 + g + 8 * nt]);
                uint32_t b1 = __float_as_uint(zs[(kg + tg + 4) * 24 + g + 8 * nt]);
                mma_tf32(acc[nt], a, b0, b1);
            }
        }

        if (kit + 2 < 8) cpA(kit + 2, kit & 1);
    }

    float bb[2];
#pragma unroll
    for (int r = 0; r < 2; r++) {
        int m = m0 + (g + 8 * r) * 1152;
        bb[r] = base_w[m] + head_b[m];
    }

    __syncthreads();                 // A stages dead, reuse as outbuf
    __half* ob = reinterpret_cast<__half*>(Aw0);  // [b][lane][4 halves]

    const int lane_o = g * 4 + (wid >> 1);
    const int hsel   = wid & 1;
#pragma unroll
    for (int nt = 0; nt < 2; nt++)
#pragma unroll
        for (int r = 0; r < 2; r++)
#pragma unroll
            for (int c = 0; c < 2; c++) {
                int b = 2 * tg + c + 8 * nt;
                ob[b * 128 + lane_o * 4 + r * 2 + hsel] =
                    __float2half_rn(bb[r] + acc[nt][r * 2 + c]);
            }
    __syncthreads();

    // coalesced write: per (b, lane) one 8B chunk
    {
        const int jc = icc * 9 + tap;
#pragma unroll
        for (int e = 0; e < 2; e++) {
            int u    = tid * 2 + e;
            int b    = u >> 5;
            int lane = u & 31;
            const uint2 v = *reinterpret_cast<const uint2*>(&ob[b * 128 + lane * 4]);
            __half* dst = g_w + ((size_t)b * 36 + jc) * 4096 +
                          tile * 512 + kstep * 256 + lane * 8 + ichalf * 4;
            *reinterpret_cast<uint2*>(dst) = v;
        }
    }
}

// ---------------------------------------------------------------------------
// Kernel 2: implicit-GEMM conv on mma.sync fp16 m16n8k16 (fp32 accumulate).
// CTA tile: M=128 oc x N=128 px (2 rows x 64 cols) x K=1152 (36 chunks of 32).
// 8 warps 4x2: each 32 oc x 64 px. Per chunk: 32 HMMA (was 64 tf32).
// A: per-warp PRIVATE 2-stage cp.async (2KB/chunk), wait_group-paced.
// B: xs2 slab of half2 (ic-pairs packed), pair-stride 296 -> conflict-free.
// SMEM: A 32KB + xs2 18.9KB = 50.5KB.
// ---------------------------------------------------------------------------
#define XS2_OFF   32768                       // bytes
#define CONV_SMEM (32768 + 16 * 296 * 4)      // 51712 bytes

__global__ __launch_bounds__(256, 2) void conv_kernel(
    const float* __restrict__ x, float* __restrict__ out)
{
    extern __shared__ char smc[];
    __half2* xs2 = reinterpret_cast<__half2*>(smc + XS2_OFF);
    const uint32_t smb = smem_u32(smc);

    const int tid  = threadIdx.x;
    const int wid  = tid >> 5;
    const int lid  = tid & 31;
    const int g    = lid >> 2;        // 0..7
    const int tg   = lid & 3;         // 0..3
    const int wm   = wid & 3;         // oc quarter (32 oc)
    const int wn   = wid >> 2;        // output row within pair
    const int pair = blockIdx.x;      // 0..31
    const int b    = blockIdx.y;      // 0..15
    const int r0   = pair * 2;

    const float* xb = x + (size_t)b * IC_ * 4096;
    const __half* wbase = g_w + (size_t)b * 36 * 4096;

    float acc[2][8][4];
#pragma unroll
    for (int mt = 0; mt < 2; mt++)
#pragma unroll
        for (int nt = 0; nt < 8; nt++)
#pragma unroll
            for (int r = 0; r < 4; r++) acc[mt][nt][r] = 0.f;

    // xs2[ic2 16][rr 4][cc 66(+pad)]: half2 = (x[2*ic2], x[2*ic2+1]) at
    // row r0-1+rr, col cc-1. pair stride 296 (mod 32 == 8 -> conflict-free).
    auto build_xs = [&](int icc) {
        for (int idx = tid; idx < 16 * 4 * 66; idx += 256) {
            int p2  = idx / 264;
            int rem = idx - p2 * 264;
            int rr  = rem / 66;
            int cc  = rem - rr * 66;
            int gr  = r0 - 1 + rr;
            int gc  = cc - 1;
            float v0 = 0.f, v1 = 0.f;
            if ((unsigned)gr < 64u && (unsigned)gc < 64u) {
                const float* xp = xb + (size_t)(icc * 32 + 2 * p2) * 4096 + gr * 64 + gc;
                v0 = xp[0];
                v1 = xp[4096];
            }
            xs2[p2 * 296 + rr * 68 + cc] = __floats2half2_rn(v0, v1);
        }
    };

    // per-warp private A copy: 2KB of fp16 fragments per chunk
    const uint32_t aw_dst0 = smb + wid * 4096 + lid * 16;
    auto cpA = [&](int j) {
        const __half* src = wbase + (size_t)j * 4096 + wm * 1024 + lid * 8;
        uint32_t dst = aw_dst0 + (j & 1) * 2048;
#pragma unroll
        for (int s = 0; s < 4; s++)            // s = mt*2 + kstep
            cp_async16(dst + s * 512, src + s * 256);
        asm volatile("cp.async.commit_group;" ::: "memory");
    };

    auto mma_chunk = [&](int stage, int kh, int kw) {
        const char* As = smc + wid * 4096 + stage * 2048 + lid * 16;
        const __half2* xw = xs2 + (wn + kh) * 68 + (kw + g);
#pragma unroll
        for (int kstep = 0; kstep < 2; kstep++) {
            uint4 fa0 = *reinterpret_cast<const uint4*>(As + (0 * 2 + kstep) * 512);
            uint4 fa1 = *reinterpret_cast<const uint4*>(As + (1 * 2 + kstep) * 512);
            uint32_t a0[4] = {fa0.x, fa0.y, fa0.z, fa0.w};
            uint32_t a1[4] = {fa1.x, fa1.y, fa1.z, fa1.w};
            const __half2* xk0 = xw + (kstep * 8 + tg) * 296;
            const __half2* xk1 = xk0 + 4 * 296;
#pragma unroll
            for (int nt = 0; nt < 8; nt++) {
                uint32_t b0 = *reinterpret_cast<const uint32_t*>(xk0 + nt * 8);
                uint32_t b1 = *reinterpret_cast<const uint32_t*>(xk1 + nt * 8);
                mma_f16(acc[0][nt], a0, b0, b1);
                mma_f16(acc[1][nt], a1, b0, b1);
            }
        }
    };

    // ---- prologue ----
    cpA(0);
    cpA(1);
    build_xs(0);
    __syncthreads();

    // ---- main loop: NO CTA barriers inside icc groups ----
    for (int icc = 0; icc < 4; icc++) {
#pragma unroll
        for (int tap = 0; tap < 9; tap++) {
            const int j  = icc * 9 + tap;
            const int kh = tap / 3;
            const int kw = tap - kh * 3;

            if (j < 34)
                asm volatile("cp.async.wait_group 1;" ::: "memory");
            else
                asm volatile("cp.async.wait_group 0;" ::: "memory");

            mma_chunk(j & 1, kh, kw);

            if (j + 2 < 36) cpA(j + 2);
        }
        if (icc < 3) {
            __syncthreads();          // all warps done reading xs2
            build_xs(icc + 1);
            __syncthreads();
        }
    }

    // ---- epilogue: acc -> out[b][oc][px] ----
#pragma unroll
    for (int mt = 0; mt < 2; mt++) {
        int oc = wm * 32 + mt * 16 + g;
#pragma unroll
        for (int nt = 0; nt < 8; nt++) {
            int n  = wn * 64 + nt * 8 + 2 * tg;
            size_t base = ((size_t)b * OC_ + oc) * 4096 + pair * 128 + n;
            float2 v0 = make_float2(acc[mt][nt][0], acc[mt][nt][1]);
            float2 v1 = make_float2(acc[mt][nt][2], acc[mt][nt][3]);
            *reinterpret_cast<float2*>(out + base)            = v0;
            *reinterpret_cast<float2*>(out + base + 8 * 4096) = v1;
        }
    }
}

// ---------------------------------------------------------------------------
extern "C" void kernel_launch(void* const* d_in, const int* in_sizes, int n_in,
                              void* d_out, int out_size) {
    const float* x      = (const float*)d_in[0];
    const float* z      = (const float*)d_in[1];
    const float* base_w = (const float*)d_in[2];
    const float* head_w = (const float*)d_in[3];
    const float* head_b = (const float*)d_in[4];
    float* out = (float*)d_out;

    static bool attr_set = false;
    if (!attr_set) {
        cudaFuncSetAttribute(conv_kernel,
                             cudaFuncAttributeMaxDynamicSharedMemorySize,
                             CONV_SMEM);
        cudaFuncSetAttribute(weight_kernel,
                             cudaFuncAttributeMaxDynamicSharedMemorySize,
                             WK_SM_FLOATS * 4);
        attr_set = true;
    }

    weight_kernel<<<1152, 256, WK_SM_FLOATS * 4>>>(z, base_w, head_w, head_b);
    conv_kernel<<<dim3(32, 16), 256, CONV_SMEM>>>(x, out);
}

// round 14
// speedup vs baseline: 1.8283x; 1.1456x over previous
#include <cuda_runtime.h>
#include <cuda_fp16.h>
#include <cstdint>

#define IC_   128
#define OC_   128
#define ZDIM_ 256
#define B_    16
#define WSIZE_ (OC_ * IC_ * 9)   // 147456

// Per-sample weights as fp16 in m16n8k16 A-fragment order:
// [b][chunk j=icc*9+tap (36)][tile (8)][kstep (2)][lane (32)][8 halves]
__device__ __half g_w[(size_t)B_ * WSIZE_];

__device__ __forceinline__ float to_tf32(float v) {
    float o;
    asm("cvt.rna.tf32.f32 %0, %1;" : "=f"(o) : "f"(v));
    return o;
}

__device__ __forceinline__ uint32_t smem_u32(const void* p) {
    uint32_t a;
    asm("{ .reg .u64 t; cvta.to.shared.u64 t, %1; cvt.u32.u64 %0, t; }" : "=r"(a) : "l"(p));
    return a;
}

__device__ __forceinline__ void cp_async16(uint32_t dst, const void* src) {
    asm volatile("cp.async.cg.shared.global [%0], [%1], 16;" :: "r"(dst), "l"(src));
}

__device__ __forceinline__ void mma_tf32(float* d, const uint32_t* a,
                                         uint32_t b0, uint32_t b1) {
    asm volatile(
        "mma.sync.aligned.m16n8k8.row.col.f32.tf32.tf32.f32 "
        "{%0,%1,%2,%3}, {%4,%5,%6,%7}, {%8,%9}, {%0,%1,%2,%3};"
        : "+f"(d[0]), "+f"(d[1]), "+f"(d[2]), "+f"(d[3])
        : "r"(a[0]), "r"(a[1]), "r"(a[2]), "r"(a[3]), "r"(b0), "r"(b1));
}

__device__ __forceinline__ void mma_f16(float* d, const uint32_t* a,
                                        uint32_t b0, uint32_t b1) {
    asm volatile(
        "mma.sync.aligned.m16n8k16.row.col.f32.f16.f16.f32 "
        "{%0,%1,%2,%3}, {%4,%5,%6,%7}, {%8,%9}, {%0,%1,%2,%3};"
        : "+f"(d[0]), "+f"(d[1]), "+f"(d[2]), "+f"(d[3])
        : "r"(a[0]), "r"(a[1]), "r"(a[2]), "r"(a[3]), "r"(b0), "r"(b1));
}

// ---------------------------------------------------------------------------
// Kernel 1: per-sample weight generation on HMMA tf32, fp16 fragment output.
// (unchanged from R13 — measured good)
// ---------------------------------------------------------------------------
#define WK_ZS_FLOATS (ZDIM_ * 24)
#define WK_AST_FLOATS 576
#define WK_SM_FLOATS (WK_ZS_FLOATS + 8 * 2 * WK_AST_FLOATS)

__global__ __launch_bounds__(256, 3) void weight_kernel(
    const float* __restrict__ z, const float* __restrict__ base_w,
    const float* __restrict__ head_w, const float* __restrict__ head_b)
{
    extern __shared__ float wsm[];
    float* zs  = wsm;
    float* Aw0 = wsm + WK_ZS_FLOATS;

    const int tid = threadIdx.x;
    const int wid = tid >> 5;
    const int lid = tid & 31;
    const int g   = lid >> 2;
    const int tg  = lid & 3;

    const int bid    = blockIdx.x;
    const int tap    = bid % 9;
    const int t      = bid / 9;
    const int ichalf = t & 1;
    const int kstep  = (t >> 1) & 1;
    const int icc    = (t >> 2) & 3;
    const int tile   = t >> 4;

    const int ic = icc * 32 + kstep * 16 + ichalf * 8 + wid;
    const int m0 = (tile * 16) * 1152 + ic * 9 + tap;

    float* Awarp = Aw0 + wid * (2 * WK_AST_FLOATS);
    const uint32_t AwarpB = smem_u32(Awarp);

    auto cpA = [&](int kit, int stage) {
        uint32_t dstb = AwarpB + stage * (WK_AST_FLOATS * 4);
        const int c4 = lid & 7;
#pragma unroll
        for (int p = 0; p < 4; p++) {
            int row = (lid >> 3) + 4 * p;
            cp_async16(dstb + (row * 36 + c4 * 4) * 4,
                       head_w + (size_t)(m0 + row * 1152) * ZDIM_ + kit * 32 + c4 * 4);
        }
        asm volatile("cp.async.commit_group;" ::: "memory");
    };

    cpA(0, 0);
    cpA(1, 1);

    for (int i = tid; i < B_ * ZDIM_; i += 256) {
        int b = i >> 8;
        int d = i & 255;
        zs[d * 24 + b] = to_tf32(z[i]);
    }

    float acc[2][4];
#pragma unroll
    for (int nt = 0; nt < 2; nt++)
#pragma unroll
        for (int r = 0; r < 4; r++) acc[nt][r] = 0.f;

    __syncthreads();

    for (int kit = 0; kit < 8; kit++) {
        if (kit < 7)
            asm volatile("cp.async.wait_group 1;" ::: "memory");
        else
            asm volatile("cp.async.wait_group 0;" ::: "memory");

        const float* As = Awarp + (kit & 1) * WK_AST_FLOATS;
#pragma unroll
        for (int ks = 0; ks < 4; ks++) {
            const int kl = ks * 8;
            uint32_t a[4];
            a[0] = __float_as_uint(to_tf32(As[g * 36 + kl + tg]));
            a[1] = __float_as_uint(to_tf32(As[(g + 8) * 36 + kl + tg]));
            a[2] = __float_as_uint(to_tf32(As[g * 36 + kl + tg + 4]));
            a[3] = __float_as_uint(to_tf32(As[(g + 8) * 36 + kl + tg + 4]));
            const int kg = kit * 32 + kl;
#pragma unroll
            for (int nt = 0; nt < 2; nt++) {
                uint32_t b0 = __float_as_uint(zs[(kg + tg) * 24 + g + 8 * nt]);
                uint32_t b1 = __float_as_uint(zs[(kg + tg + 4) * 24 + g + 8 * nt]);
                mma_tf32(acc[nt], a, b0, b1);
            }
        }

        if (kit + 2 < 8) cpA(kit + 2, kit & 1);
    }

    float bb[2];
#pragma unroll
    for (int r = 0; r < 2; r++) {
        int m = m0 + (g + 8 * r) * 1152;
        bb[r] = base_w[m] + head_b[m];
    }

    __syncthreads();
    __half* ob = reinterpret_cast<__half*>(Aw0);

    const int lane_o = g * 4 + (wid >> 1);
    const int hsel   = wid & 1;
#pragma unroll
    for (int nt = 0; nt < 2; nt++)
#pragma unroll
        for (int r = 0; r < 2; r++)
#pragma unroll
            for (int c = 0; c < 2; c++) {
                int b = 2 * tg + c + 8 * nt;
                ob[b * 128 + lane_o * 4 + r * 2 + hsel] =
                    __float2half_rn(bb[r] + acc[nt][r * 2 + c]);
            }
    __syncthreads();

    {
        const int jc = icc * 9 + tap;
#pragma unroll
        for (int e = 0; e < 2; e++) {
            int u    = tid * 2 + e;
            int b    = u >> 5;
            int lane = u & 31;
            const uint2 v = *reinterpret_cast<const uint2*>(&ob[b * 128 + lane * 4]);
            __half* dst = g_w + ((size_t)b * 36 + jc) * 4096 +
                          tile * 512 + kstep * 256 + lane * 8 + ichalf * 4;
            *reinterpret_cast<uint2*>(dst) = v;
        }
    }
}

// ---------------------------------------------------------------------------
// Kernel 2: implicit-GEMM conv on mma.sync fp16 m16n8k16 (fp32 accumulate).
// CTA tile: M=128 oc x N=128 px x K=1152 (36 chunks of 32). 8 warps 4x2.
// A: per-warp PRIVATE 2-stage cp.async, wait_group-paced, no CTA barriers
//    except icc-group boundaries.
// B: DOUBLE-BUFFERED xs2 slab of half2; build for group icc+1 overlapped
//    after tap 0's MMA of group icc; only 4 CTA barriers total.
// SMEM: A 32KB + 2 x xs2 18.5KB = 69KB.
// ---------------------------------------------------------------------------
#define XS2_BYTES (16 * 296 * 4)                    // 18944 per buffer
#define CONV_SMEM (32768 + 2 * XS2_BYTES)           // 70656 bytes

__global__ __launch_bounds__(256, 2) void conv_kernel(
    const float* __restrict__ x, float* __restrict__ out)
{
    extern __shared__ char smc[];
    const uint32_t smb = smem_u32(smc);

    const int tid  = threadIdx.x;
    const int wid  = tid >> 5;
    const int lid  = tid & 31;
    const int g    = lid >> 2;        // 0..7
    const int tg   = lid & 3;         // 0..3
    const int wm   = wid & 3;         // oc quarter (32 oc)
    const int wn   = wid >> 2;        // output row within pair
    const int pair = blockIdx.x;      // 0..31
    const int b    = blockIdx.y;      // 0..15
    const int r0   = pair * 2;

    const float* xb = x + (size_t)b * IC_ * 4096;
    const __half* wbase = g_w + (size_t)b * 36 * 4096;

    float acc[2][8][4];
#pragma unroll
    for (int mt = 0; mt < 2; mt++)
#pragma unroll
        for (int nt = 0; nt < 8; nt++)
#pragma unroll
            for (int r = 0; r < 4; r++) acc[mt][nt][r] = 0.f;

    auto xsbuf = [&](int q) {
        return reinterpret_cast<__half2*>(smc + 32768 + q * XS2_BYTES);
    };

    // xs2[p2 16][rr 4][cc 66(+pad)]: half2 = (x[2p2], x[2p2+1]) at row
    // r0-1+rr, col cc-1. pair stride 296. Vectorized interior, zero borders.
    auto build_xs = [&](int icc, int q) {
        __half2* xs2 = xsbuf(q);
        // interior: cc = 1..64 (pixels 0..63), float4 x 2 channels per idx
        for (int idx = tid; idx < 1024; idx += 256) {
            int p2  = idx >> 6;               // 0..15
            int rem = idx & 63;
            int rr  = rem >> 4;               // 0..3
            int qd  = rem & 15;               // 0..15 quad
            int gr  = r0 - 1 + rr;
            float4 a0 = make_float4(0.f, 0.f, 0.f, 0.f);
            float4 a1 = a0;
            if ((unsigned)gr < 64u) {
                const float* xp = xb + (size_t)(icc * 32 + 2 * p2) * 4096 + gr * 64 + qd * 4;
                a0 = *reinterpret_cast<const float4*>(xp);
                a1 = *reinterpret_cast<const float4*>(xp + 4096);
            }
            __half2* dst = xs2 + p2 * 296 + rr * 68 + 1 + qd * 4;
            dst[0] = __floats2half2_rn(a0.x, a1.x);
            dst[1] = __floats2half2_rn(a0.y, a1.y);
            dst[2] = __floats2half2_rn(a0.z, a1.z);
            dst[3] = __floats2half2_rn(a0.w, a1.w);
        }
        // borders cc=0 and cc=65: always outside the image -> zero
        if (tid < 128) {
            int p2   = tid >> 3;
            int rr   = (tid >> 1) & 3;
            int side = tid & 1;
            xs2[p2 * 296 + rr * 68 + side * 65] = __half2half2(__float2half(0.f));
        }
    };

    // per-warp private A copy: 2KB of fp16 fragments per chunk
    const uint32_t aw_dst0 = smb + wid * 4096 + lid * 16;
    auto cpA = [&](int j) {
        const __half* src = wbase + (size_t)j * 4096 + wm * 1024 + lid * 8;
        uint32_t dst = aw_dst0 + (j & 1) * 2048;
#pragma unroll
        for (int s = 0; s < 4; s++)
            cp_async16(dst + s * 512, src + s * 256);
        asm volatile("cp.async.commit_group;" ::: "memory");
    };

    auto mma_chunk = [&](int stage, const __half2* xs2, int kh, int kw) {
        const char* As = smc + wid * 4096 + stage * 2048 + lid * 16;
        const __half2* xw = xs2 + (wn + kh) * 68 + (kw + g);
#pragma unroll
        for (int kstep = 0; kstep < 2; kstep++) {
            uint4 fa0 = *reinterpret_cast<const uint4*>(As + (0 * 2 + kstep) * 512);
            uint4 fa1 = *reinterpret_cast<const uint4*>(As + (1 * 2 + kstep) * 512);
            uint32_t a0[4] = {fa0.x, fa0.y, fa0.z, fa0.w};
            uint32_t a1[4] = {fa1.x, fa1.y, fa1.z, fa1.w};
            const __half2* xk0 = xw + (kstep * 8 + tg) * 296;
            const __half2* xk1 = xk0 + 4 * 296;
#pragma unroll
            for (int nt = 0; nt < 8; nt++) {
                uint32_t b0 = *reinterpret_cast<const uint32_t*>(xk0 + nt * 8);
                uint32_t b1 = *reinterpret_cast<const uint32_t*>(xk1 + nt * 8);
                mma_f16(acc[0][nt], a0, b0, b1);
                mma_f16(acc[1][nt], a1, b0, b1);
            }
        }
    };

    // ---- prologue ----
    cpA(0);
    cpA(1);
    build_xs(0, 0);
    __syncthreads();

    // ---- main loop: 1 barrier per icc boundary, builds overlapped ----
    for (int icc = 0; icc < 4; icc++) {
        const __half2* xcur = xsbuf(icc & 1);
#pragma unroll
        for (int tap = 0; tap < 9; tap++) {
            const int j  = icc * 9 + tap;
            const int kh = tap / 3;
            const int kw = tap - kh * 3;

            if (j < 34)
                asm volatile("cp.async.wait_group 1;" ::: "memory");
            else
                asm volatile("cp.async.wait_group 0;" ::: "memory");

            mma_chunk(j & 1, xcur, kh, kw);

            if (j + 2 < 36) cpA(j + 2);

            if (tap == 0 && icc < 3)
                build_xs(icc + 1, (icc + 1) & 1);   // overlapped with taps 1..8
        }
        if (icc < 3)
            __syncthreads();   // new buffer visible; old buffer reads done
    }

    // ---- epilogue: acc -> out[b][oc][px] ----
#pragma unroll
    for (int mt = 0; mt < 2; mt++) {
        int oc = wm * 32 + mt * 16 + g;
#pragma unroll
        for (int nt = 0; nt < 8; nt++) {
            int n  = wn * 64 + nt * 8 + 2 * tg;
            size_t base = ((size_t)b * OC_ + oc) * 4096 + pair * 128 + n;
            float2 v0 = make_float2(acc[mt][nt][0], acc[mt][nt][1]);
            float2 v1 = make_float2(acc[mt][nt][2], acc[mt][nt][3]);
            *reinterpret_cast<float2*>(out + base)            = v0;
            *reinterpret_cast<float2*>(out + base + 8 * 4096) = v1;
        }
    }
}

// ---------------------------------------------------------------------------
extern "C" void kernel_launch(void* const* d_in, const int* in_sizes, int n_in,
                              void* d_out, int out_size) {
    const float* x      = (const float*)d_in[0];
    const float* z      = (const float*)d_in[1];
    const float* base_w = (const float*)d_in[2];
    const float* head_w = (const float*)d_in[3];
    const float* head_b = (const float*)d_in[4];
    float* out = (float*)d_out;

    static bool attr_set = false;
    if (!attr_set) {
        cudaFuncSetAttribute(conv_kernel,
                             cudaFuncAttributeMaxDynamicSharedMemorySize,
                             CONV_SMEM);
        cudaFuncSetAttribute(weight_kernel,
                             cudaFuncAttributeMaxDynamicSharedMemorySize,
                             WK_SM_FLOATS * 4);
        attr_set = true;
    }

    weight_kernel<<<1152, 256, WK_SM_FLOATS * 4>>>(z, base_w, head_w, head_b);
    conv_kernel<<<dim3(32, 16), 256, CONV_SMEM>>>(x, out);
}

// round 15
// speedup vs baseline: 1.8914x; 1.0345x over previous
#include <cuda_runtime.h>
#include <cuda_fp16.h>
#include <cstdint>

#define IC_   128
#define OC_   128
#define ZDIM_ 256
#define B_    16
#define WSIZE_ (OC_ * IC_ * 9)   // 147456

// Per-sample weights as fp16 in m16n8k16 A-fragment order:
// [b][chunk j=icc*9+tap (36)][tile (8)][kstep (2)][lane (32)][8 halves]
__device__ __half g_w[(size_t)B_ * WSIZE_];

__device__ __forceinline__ float to_tf32(float v) {
    float o;
    asm("cvt.rna.tf32.f32 %0, %1;" : "=f"(o) : "f"(v));
    return o;
}

__device__ __forceinline__ uint32_t smem_u32(const void* p) {
    uint32_t a;
    asm("{ .reg .u64 t; cvta.to.shared.u64 t, %1; cvt.u32.u64 %0, t; }" : "=r"(a) : "l"(p));
    return a;
}

__device__ __forceinline__ void cp_async16(uint32_t dst, const void* src) {
    asm volatile("cp.async.cg.shared.global [%0], [%1], 16;" :: "r"(dst), "l"(src));
}

__device__ __forceinline__ void mma_tf32(float* d, const uint32_t* a,
                                         uint32_t b0, uint32_t b1) {
    asm volatile(
        "mma.sync.aligned.m16n8k8.row.col.f32.tf32.tf32.f32 "
        "{%0,%1,%2,%3}, {%4,%5,%6,%7}, {%8,%9}, {%0,%1,%2,%3};"
        : "+f"(d[0]), "+f"(d[1]), "+f"(d[2]), "+f"(d[3])
        : "r"(a[0]), "r"(a[1]), "r"(a[2]), "r"(a[3]), "r"(b0), "r"(b1));
}

__device__ __forceinline__ void mma_f16(float* d, const uint32_t* a,
                                        uint32_t b0, uint32_t b1) {
    asm volatile(
        "mma.sync.aligned.m16n8k16.row.col.f32.f16.f16.f32 "
        "{%0,%1,%2,%3}, {%4,%5,%6,%7}, {%8,%9}, {%0,%1,%2,%3};"
        : "+f"(d[0]), "+f"(d[1]), "+f"(d[2]), "+f"(d[3])
        : "r"(a[0]), "r"(a[1]), "r"(a[2]), "r"(a[3]), "r"(b0), "r"(b1));
}

// ---------------------------------------------------------------------------
// Kernel 1: per-sample weight generation on HMMA tf32, fp16 fragment output.
// zs stored as fp16 (mantissa == tf32 mantissa; f16->f32 exact). smem 48KB ->
// 4 CTAs/SM -> 1.95 waves (was 2.59). No CTA barriers in the k-loop.
// ---------------------------------------------------------------------------
#define WK_ZS_BYTES (ZDIM_ * 24 * 2)          // 12288
#define WK_AST_FLOATS 576                     // one stage: 16 rows x 36 pitch
#define WK_SM_BYTES (WK_ZS_BYTES + 8 * 2 * WK_AST_FLOATS * 4)   // 49152

__global__ __launch_bounds__(256, 4) void weight_kernel(
    const float* __restrict__ z, const float* __restrict__ base_w,
    const float* __restrict__ head_w, const float* __restrict__ head_b)
{
    extern __shared__ char wsmc[];
    __half* zsh = reinterpret_cast<__half*>(wsmc);              // [256 k][24 pitch]
    float*  Aw0 = reinterpret_cast<float*>(wsmc + WK_ZS_BYTES); // warp A stages

    const int tid = threadIdx.x;
    const int wid = tid >> 5;
    const int lid = tid & 31;
    const int g   = lid >> 2;
    const int tg  = lid & 3;

    const int bid    = blockIdx.x;
    const int tap    = bid % 9;
    const int t      = bid / 9;
    const int ichalf = t & 1;
    const int kstep  = (t >> 1) & 1;
    const int icc    = (t >> 2) & 3;
    const int tile   = t >> 4;

    const int ic = icc * 32 + kstep * 16 + ichalf * 8 + wid;
    const int m0 = (tile * 16) * 1152 + ic * 9 + tap;

    float* Awarp = Aw0 + wid * (2 * WK_AST_FLOATS);
    const uint32_t AwarpB = smem_u32(Awarp);

    auto cpA = [&](int kit, int stage) {
        uint32_t dstb = AwarpB + stage * (WK_AST_FLOATS * 4);
        const int c4 = lid & 7;
#pragma unroll
        for (int p = 0; p < 4; p++) {
            int row = (lid >> 3) + 4 * p;
            cp_async16(dstb + (row * 36 + c4 * 4) * 4,
                       head_w + (size_t)(m0 + row * 1152) * ZDIM_ + kit * 32 + c4 * 4);
        }
        asm volatile("cp.async.commit_group;" ::: "memory");
    };

    cpA(0, 0);
    cpA(1, 1);

    // z -> zs (fp16, [k][b] pitch 24)
    for (int i = tid; i < B_ * ZDIM_; i += 256) {
        int b = i >> 8;
        int d = i & 255;
        zsh[d * 24 + b] = __float2half_rn(z[i]);
    }

    float acc[2][4];
#pragma unroll
    for (int nt = 0; nt < 2; nt++)
#pragma unroll
        for (int r = 0; r < 4; r++) acc[nt][r] = 0.f;

    __syncthreads();

    for (int kit = 0; kit < 8; kit++) {
        if (kit < 7)
            asm volatile("cp.async.wait_group 1;" ::: "memory");
        else
            asm volatile("cp.async.wait_group 0;" ::: "memory");

        const float* As = Awarp + (kit & 1) * WK_AST_FLOATS;
#pragma unroll
        for (int ks = 0; ks < 4; ks++) {
            const int kl = ks * 8;
            uint32_t a[4];
            a[0] = __float_as_uint(to_tf32(As[g * 36 + kl + tg]));
            a[1] = __float_as_uint(to_tf32(As[(g + 8) * 36 + kl + tg]));
            a[2] = __float_as_uint(to_tf32(As[g * 36 + kl + tg + 4]));
            a[3] = __float_as_uint(to_tf32(As[(g + 8) * 36 + kl + tg + 4]));
            const int kg = kit * 32 + kl;
#pragma unroll
            for (int nt = 0; nt < 2; nt++) {
                uint32_t b0 = __float_as_uint(__half2float(zsh[(kg + tg) * 24 + g + 8 * nt]));
                uint32_t b1 = __float_as_uint(__half2float(zsh[(kg + tg + 4) * 24 + g + 8 * nt]));
                mma_tf32(acc[nt], a, b0, b1);
            }
        }

        if (kit + 2 < 8) cpA(kit + 2, kit & 1);
    }

    float bb[2];
#pragma unroll
    for (int r = 0; r < 2; r++) {
        int m = m0 + (g + 8 * r) * 1152;
        bb[r] = base_w[m] + head_b[m];
    }

    __syncthreads();                 // A stages dead, reuse as outbuf
    __half* ob = reinterpret_cast<__half*>(Aw0);  // [b][lane][4 halves]

    const int lane_o = g * 4 + (wid >> 1);
    const int hsel   = wid & 1;
#pragma unroll
    for (int nt = 0; nt < 2; nt++)
#pragma unroll
        for (int r = 0; r < 2; r++)
#pragma unroll
            for (int c = 0; c < 2; c++) {
                int b = 2 * tg + c + 8 * nt;
                ob[b * 128 + lane_o * 4 + r * 2 + hsel] =
                    __float2half_rn(bb[r] + acc[nt][r * 2 + c]);
            }
    __syncthreads();

    {
        const int jc = icc * 9 + tap;
#pragma unroll
        for (int e = 0; e < 2; e++) {
            int u    = tid * 2 + e;
            int b    = u >> 5;
            int lane = u & 31;
            const uint2 v = *reinterpret_cast<const uint2*>(&ob[b * 128 + lane * 4]);
            __half* dst = g_w + ((size_t)b * 36 + jc) * 4096 +
                          tile * 512 + kstep * 256 + lane * 8 + ichalf * 4;
            *reinterpret_cast<uint2*>(dst) = v;
        }
    }
}

// ---------------------------------------------------------------------------
// Kernel 2: implicit-GEMM conv on mma.sync fp16 m16n8k16 (fp32 accumulate).
// [R14 best config — unchanged]
// ---------------------------------------------------------------------------
#define XS2_BYTES (16 * 296 * 4)                    // 18944 per buffer
#define CONV_SMEM (32768 + 2 * XS2_BYTES)           // 70656 bytes

__global__ __launch_bounds__(256, 2) void conv_kernel(
    const float* __restrict__ x, float* __restrict__ out)
{
    extern __shared__ char smc[];
    const uint32_t smb = smem_u32(smc);

    const int tid  = threadIdx.x;
    const int wid  = tid >> 5;
    const int lid  = tid & 31;
    const int g    = lid >> 2;        // 0..7
    const int tg   = lid & 3;         // 0..3
    const int wm   = wid & 3;         // oc quarter (32 oc)
    const int wn   = wid >> 2;        // output row within pair
    const int pair = blockIdx.x;      // 0..31
    const int b    = blockIdx.y;      // 0..15
    const int r0   = pair * 2;

    const float* xb = x + (size_t)b * IC_ * 4096;
    const __half* wbase = g_w + (size_t)b * 36 * 4096;

    float acc[2][8][4];
#pragma unroll
    for (int mt = 0; mt < 2; mt++)
#pragma unroll
        for (int nt = 0; nt < 8; nt++)
#pragma unroll
            for (int r = 0; r < 4; r++) acc[mt][nt][r] = 0.f;

    auto xsbuf = [&](int q) {
        return reinterpret_cast<__half2*>(smc + 32768 + q * XS2_BYTES);
    };

    auto build_xs = [&](int icc, int q) {
        __half2* xs2 = xsbuf(q);
        for (int idx = tid; idx < 1024; idx += 256) {
            int p2  = idx >> 6;
            int rem = idx & 63;
            int rr  = rem >> 4;
            int qd  = rem & 15;
            int gr  = r0 - 1 + rr;
            float4 a0 = make_float4(0.f, 0.f, 0.f, 0.f);
            float4 a1 = a0;
            if ((unsigned)gr < 64u) {
                const float* xp = xb + (size_t)(icc * 32 + 2 * p2) * 4096 + gr * 64 + qd * 4;
                a0 = *reinterpret_cast<const float4*>(xp);
                a1 = *reinterpret_cast<const float4*>(xp + 4096);
            }
            __half2* dst = xs2 + p2 * 296 + rr * 68 + 1 + qd * 4;
            dst[0] = __floats2half2_rn(a0.x, a1.x);
            dst[1] = __floats2half2_rn(a0.y, a1.y);
            dst[2] = __floats2half2_rn(a0.z, a1.z);
            dst[3] = __floats2half2_rn(a0.w, a1.w);
        }
        if (tid < 128) {
            int p2   = tid >> 3;
            int rr   = (tid >> 1) & 3;
            int side = tid & 1;
            xs2[p2 * 296 + rr * 68 + side * 65] = __half2half2(__float2half(0.f));
        }
    };

    const uint32_t aw_dst0 = smb + wid * 4096 + lid * 16;
    auto cpA = [&](int j) {
        const __half* src = wbase + (size_t)j * 4096 + wm * 1024 + lid * 8;
        uint32_t dst = aw_dst0 + (j & 1) * 2048;
#pragma unroll
        for (int s = 0; s < 4; s++)
            cp_async16(dst + s * 512, src + s * 256);
        asm volatile("cp.async.commit_group;" ::: "memory");
    };

    auto mma_chunk = [&](int stage, const __half2* xs2, int kh, int kw) {
        const char* As = smc + wid * 4096 + stage * 2048 + lid * 16;
        const __half2* xw = xs2 + (wn + kh) * 68 + (kw + g);
#pragma unroll
        for (int kstep = 0; kstep < 2; kstep++) {
            uint4 fa0 = *reinterpret_cast<const uint4*>(As + (0 * 2 + kstep) * 512);
            uint4 fa1 = *reinterpret_cast<const uint4*>(As + (1 * 2 + kstep) * 512);
            uint32_t a0[4] = {fa0.x, fa0.y, fa0.z, fa0.w};
            uint32_t a1[4] = {fa1.x, fa1.y, fa1.z, fa1.w};
            const __half2* xk0 = xw + (kstep * 8 + tg) * 296;
            const __half2* xk1 = xk0 + 4 * 296;
#pragma unroll
            for (int nt = 0; nt < 8; nt++) {
                uint32_t b0 = *reinterpret_cast<const uint32_t*>(xk0 + nt * 8);
                uint32_t b1 = *reinterpret_cast<const uint32_t*>(xk1 + nt * 8);
                mma_f16(acc[0][nt], a0, b0, b1);
                mma_f16(acc[1][nt], a1, b0, b1);
            }
        }
    };

    // ---- prologue ----
    cpA(0);
    cpA(1);
    build_xs(0, 0);
    __syncthreads();

    // ---- main loop ----
    for (int icc = 0; icc < 4; icc++) {
        const __half2* xcur = xsbuf(icc & 1);
#pragma unroll
        for (int tap = 0; tap < 9; tap++) {
            const int j  = icc * 9 + tap;
            const int kh = tap / 3;
            const int kw = tap - kh * 3;

            if (j < 34)
                asm volatile("cp.async.wait_group 1;" ::: "memory");
            else
                asm volatile("cp.async.wait_group 0;" ::: "memory");

            mma_chunk(j & 1, xcur, kh, kw);

            if (j + 2 < 36) cpA(j + 2);

            if (tap == 0 && icc < 3)
                build_xs(icc + 1, (icc + 1) & 1);
        }
        if (icc < 3)
            __syncthreads();
    }

    // ---- epilogue ----
#pragma unroll
    for (int mt = 0; mt < 2; mt++) {
        int oc = wm * 32 + mt * 16 + g;
#pragma unroll
        for (int nt = 0; nt < 8; nt++) {
            int n  = wn * 64 + nt * 8 + 2 * tg;
            size_t base = ((size_t)b * OC_ + oc) * 4096 + pair * 128 + n;
            float2 v0 = make_float2(acc[mt][nt][0], acc[mt][nt][1]);
            float2 v1 = make_float2(acc[mt][nt][2], acc[mt][nt][3]);
            *reinterpret_cast<float2*>(out + base)            = v0;
            *reinterpret_cast<float2*>(out + base + 8 * 4096) = v1;
        }
    }
}

// ---------------------------------------------------------------------------
extern "C" void kernel_launch(void* const* d_in, const int* in_sizes, int n_in,
                              void* d_out, int out_size) {
    const float* x      = (const float*)d_in[0];
    const float* z      = (const float*)d_in[1];
    const float* base_w = (const float*)d_in[2];
    const float* head_w = (const float*)d_in[3];
    const float* head_b = (const float*)d_in[4];
    float* out = (float*)d_out;

    static bool attr_set = false;
    if (!attr_set) {
        cudaFuncSetAttribute(conv_kernel,
                             cudaFuncAttributeMaxDynamicSharedMemorySize,
                             CONV_SMEM);
        cudaFuncSetAttribute(weight_kernel,
                             cudaFuncAttributeMaxDynamicSharedMemorySize,
                             WK_SM_BYTES);
        attr_set = true;
    }

    weight_kernel<<<1152, 256, WK_SM_BYTES>>>(z, base_w, head_w, head_b);
    conv_kernel<<<dim3(32, 16), 256, CONV_SMEM>>>(x, out);
}